// round 4
// baseline (speedup 1.0000x reference)
#include <cuda_runtime.h>
#include <cuda_bf16.h>
#include <stdint.h>

#define NB  16
#define SLQ 2048
#define SLK 2048
#define SDQ 768
#define SDK 1024

// ---------------------------------------------------------------------------
// Device-global scratch (no allocation allowed in kernel_launch).
// int8 limb pairs (q0 + q1/128)*scale ; per-row fp32 scales.
// ---------------------------------------------------------------------------
__device__ int8_t g_q0 [(size_t)NB*SLQ*SDQ];  __device__ int8_t g_q1 [(size_t)NB*SLQ*SDQ];
__device__ int8_t g_k0 [(size_t)NB*SLK*SDK];  __device__ int8_t g_k1 [(size_t)NB*SLK*SDK];
__device__ int8_t g_wq0[SDK*SDQ];             __device__ int8_t g_wq1[SDK*SDQ];
__device__ int8_t g_wk0[SDK*SDK];             __device__ int8_t g_wk1[SDK*SDK];
__device__ int8_t g_wv0[SDK*SDK];             __device__ int8_t g_wv1[SDK*SDK];
__device__ int8_t g_qp0[(size_t)NB*SLQ*SDK];  __device__ int8_t g_qp1[(size_t)NB*SLQ*SDK];
__device__ int8_t g_kp0[(size_t)NB*SLK*SDK];  __device__ int8_t g_kp1[(size_t)NB*SLK*SDK];
__device__ int8_t g_vt0[(size_t)NB*SDK*SLK];  __device__ int8_t g_vt1[(size_t)NB*SDK*SLK];
__device__ int8_t g_w0 [(size_t)NB*SLQ*SLK];  __device__ int8_t g_w1 [(size_t)NB*SLQ*SLK];

__device__ float g_s_q [NB*SLQ];   // query row scales
__device__ float g_s_k [NB*SLK];   // key row scales
__device__ float g_s_wq[SDK];      // WqT row scales (out-dims)
__device__ float g_s_wk[SDK];
__device__ float g_s_wv[SDK];
__device__ float g_s_qp[NB*SLQ];
__device__ float g_s_kp[NB*SLK];
__device__ float g_s_vt[NB*SDK];
__device__ float g_s_w [NB*SLQ];   // softmax weight row scales

__device__ float g_F[(size_t)NB*SLK*SDK];   // fp32 staging (Qp/Kp/Vt reuse)
__device__ float g_S[(size_t)NB*SLQ*SLK];   // fp32 scores

// ---------------------------------------------------------------------------
// PTX helpers (baseline sm_80-class features only)
// ---------------------------------------------------------------------------
__device__ __forceinline__ uint32_t smem_u32(const void* p) {
    uint32_t a;
    asm("{ .reg .u64 t; cvta.to.shared.u64 t, %1; cvt.u32.u64 %0, t; }"
        : "=r"(a) : "l"(p));
    return a;
}
__device__ __forceinline__ void cpa16(uint32_t dst, const void* src) {
    asm volatile("cp.async.cg.shared.global [%0], [%1], 16;"
                 :: "r"(dst), "l"(src) : "memory");
}
__device__ __forceinline__ void cpa_commit() {
    asm volatile("cp.async.commit_group;" ::: "memory");
}
template<int N>
__device__ __forceinline__ void cpa_wait() {
    asm volatile("cp.async.wait_group %0;" :: "n"(N) : "memory");
}
__device__ __forceinline__ void ldmx4(uint32_t* r, uint32_t addr) {
    asm volatile("ldmatrix.sync.aligned.m8n8.x4.shared.b16 {%0,%1,%2,%3}, [%4];"
                 : "=r"(r[0]), "=r"(r[1]), "=r"(r[2]), "=r"(r[3]) : "r"(addr));
}
// int8 MMA, s32 accumulate: D[16x8] += A[16x32] * B[32x8]
__device__ __forceinline__ void imma16832(int* c, const uint32_t* a, const uint32_t* b) {
    asm volatile(
        "mma.sync.aligned.m16n8k32.row.col.s32.s8.s8.s32 "
        "{%0,%1,%2,%3}, {%4,%5,%6,%7}, {%8,%9}, {%0,%1,%2,%3};"
        : "+r"(c[0]), "+r"(c[1]), "+r"(c[2]), "+r"(c[3])
        : "r"(a[0]), "r"(a[1]), "r"(a[2]), "r"(a[3]), "r"(b[0]), "r"(b[1]));
}
__device__ __forceinline__ uint32_t sw128(uint32_t o) { return o ^ ((o >> 3) & 0x70); }

// quantize x (given inv = 127/rowmax) into two limbs
__device__ __forceinline__ void quant2(float x, float inv, int8_t& o0, int8_t& o1) {
    float t  = x * inv;                 // in [-127,127]
    float r0 = rintf(t);
    float r1 = rintf((t - r0) * 128.f); // in [-64,64]
    o0 = (int8_t)(int)r0;
    o1 = (int8_t)(int)r1;
}

// ---------------------------------------------------------------------------
// int8 3-pass IMMA GEMM:  C[M,N] = alpha*sA[m]*sB[n]*(A@B^T) (+ bias), fp32 out
//   A limbs [M,K] K-major; B limbs [N,K] K-major. K multiple of 128.
//   CTA 128x128, chunk k=128 (128B rows, SW128), 3-stage cp.async,
//   8 warps (2m x 4n), warp tile 64x32, mma.m16n8k32.s8.
//   Passes: A0*B0 -> c_hi ; A0*B1 + A1*B0 -> c_lo ; val = hi + lo/128.
// BIASMODE: 0 = none; 1 = bias per column; 2 = bias per row
// ---------------------------------------------------------------------------
#define BM 128
#define BN 128
#define BKB 128                 // k elems (= bytes) per chunk
#define OFF_A1 16384
#define OFF_B0 32768
#define OFF_B1 49152
#define STAGE  65536
#define NSTAGE 3
#define GEMM_SMEM (NSTAGE*STAGE)   // 196608

template<int BIASMODE>
__global__ void __launch_bounds__(256, 1) imma_gemm(
    const int8_t* __restrict__ A0, const int8_t* __restrict__ A1,
    const int8_t* __restrict__ B0, const int8_t* __restrict__ B1,
    const float* __restrict__ sA, const float* __restrict__ sB,
    const float* __restrict__ bias, float* __restrict__ C,
    int N, int K, float alpha,
    long batchA, long batchB, long batchC, int sAb, int sBb)
{
    extern __shared__ char smem[];
    const uint32_t sbase = smem_u32(smem);
    const int tid  = threadIdx.x;
    const int lane = tid & 31;
    const int wid  = tid >> 5;
    const int wm   = wid >> 2;   // 0..1
    const int wn   = wid & 3;    // 0..3
    const int row0 = blockIdx.y * BM;
    const int col0 = blockIdx.x * BN;
    const size_t zA = (size_t)blockIdx.z * batchA;
    const size_t zB = (size_t)blockIdx.z * batchB;
    const size_t zC = (size_t)blockIdx.z * batchC;
    const float* sAp = sA + blockIdx.z * sAb;
    const float* sBp = sB + blockIdx.z * sBb;

    const int r8 = tid >> 3;              // 0..31
    const uint32_t cb = (tid & 7) * 16;   // byte offset within 128B row

    auto load_stage = [&](int s, int k0) {
        const uint32_t st = sbase + s * STAGE;
        #pragma unroll
        for (int i = 0; i < 4; i++) {
            int r = r8 + i * 32;
            size_t go = zA + (size_t)(row0 + r) * K + k0 + cb;
            uint32_t so = sw128((uint32_t)(r * 128) + cb);
            cpa16(st + so,          A0 + go);
            cpa16(st + OFF_A1 + so, A1 + go);
        }
        #pragma unroll
        for (int i = 0; i < 4; i++) {
            int r = r8 + i * 32;
            size_t go = zB + (size_t)(col0 + r) * K + k0 + cb;
            uint32_t so = sw128((uint32_t)(r * 128) + cb);
            cpa16(st + OFF_B0 + so, B0 + go);
            cpa16(st + OFF_B1 + so, B1 + go);
        }
        cpa_commit();
    };

    int chi[4][4][4], clo[4][4][4];
    #pragma unroll
    for (int i = 0; i < 4; i++)
        #pragma unroll
        for (int j = 0; j < 4; j++)
            #pragma unroll
            for (int k = 0; k < 4; k++) { chi[i][j][k] = 0; clo[i][j][k] = 0; }

    const int nk = K / BKB;
    load_stage(0, 0);
    load_stage(1, BKB);

    // ldmatrix lane address components (identical byte layout to bf16 case)
    const int a_r = ((lane >> 3) & 1) * 8 + (lane & 7);
    const int a_k = ((lane >> 4) & 1) * 16;
    const int b_r = ((lane >> 4) & 1) * 8 + (lane & 7);
    const int b_k = ((lane >> 3) & 1) * 16;

    for (int i = 0; i < nk; i++) {
        if (i + 1 < nk) cpa_wait<1>(); else cpa_wait<0>();
        __syncthreads();
        if (i + 2 < nk) load_stage((i + 2) % NSTAGE, (i + 2) * BKB);

        const uint32_t st = sbase + (i % NSTAGE) * STAGE;
        #pragma unroll
        for (int ks = 0; ks < 4; ks++) {           // k32 sub-steps
            uint32_t a0[4][4], a1[4][4];
            #pragma unroll
            for (int fm = 0; fm < 4; fm++) {
                int row = wm * 64 + fm * 16 + a_r;
                uint32_t so = sw128((uint32_t)(row * 128) + ks * 32 + a_k);
                ldmx4(a0[fm], st + so);
                ldmx4(a1[fm], st + OFF_A1 + so);
            }
            uint32_t b0_[2][4], b1_[2][4];
            #pragma unroll
            for (int g = 0; g < 2; g++) {
                int row = wn * 32 + g * 16 + b_r;
                uint32_t so = sw128((uint32_t)(row * 128) + ks * 32 + b_k);
                ldmx4(b0_[g], st + OFF_B0 + so);
                ldmx4(b1_[g], st + OFF_B1 + so);
            }
            #pragma unroll
            for (int fm = 0; fm < 4; fm++)
                #pragma unroll
                for (int fn = 0; fn < 4; fn++) {
                    const uint32_t* bb0 = &b0_[fn >> 1][(fn & 1) * 2];
                    const uint32_t* bb1 = &b1_[fn >> 1][(fn & 1) * 2];
                    imma16832(chi[fm][fn], a0[fm], bb0);
                    imma16832(clo[fm][fn], a0[fm], bb1);
                    imma16832(clo[fm][fn], a1[fm], bb0);
                }
        }
    }

    // ---- epilogue: dequant fragments -> fp32 global ---------------------
    #pragma unroll
    for (int fm = 0; fm < 4; fm++) {
        int row = row0 + wm * 64 + fm * 16 + (lane >> 2);
        float f0 = sAp[row] * alpha;
        float f1 = sAp[row + 8] * alpha;
        #pragma unroll
        for (int fn = 0; fn < 4; fn++) {
            int col = col0 + wn * 32 + fn * 8 + (lane & 3) * 2;
            float sb0 = sBp[col], sb1 = sBp[col + 1];
            const float inv128 = 1.f / 128.f;
            float v0 = ((float)chi[fm][fn][0] + (float)clo[fm][fn][0] * inv128) * f0 * sb0;
            float v1 = ((float)chi[fm][fn][1] + (float)clo[fm][fn][1] * inv128) * f0 * sb1;
            float v2 = ((float)chi[fm][fn][2] + (float)clo[fm][fn][2] * inv128) * f1 * sb0;
            float v3 = ((float)chi[fm][fn][3] + (float)clo[fm][fn][3] * inv128) * f1 * sb1;
            if (BIASMODE == 1) {
                float b0 = bias[col], b1 = bias[col + 1];
                v0 += b0; v1 += b1; v2 += b0; v3 += b1;
            }
            if (BIASMODE == 2) {
                float rb0 = bias[row], rb1 = bias[row + 8];
                v0 += rb0; v1 += rb0; v2 += rb1; v3 += rb1;
            }
            size_t o0 = zC + (size_t)row * N + col;
            size_t o1 = o0 + (size_t)8 * N;
            *(float2*)(C + o0) = make_float2(v0, v1);
            *(float2*)(C + o1) = make_float2(v2, v3);
        }
    }
}

// ---------------------------------------------------------------------------
// Row quantize: one block per row of length L = EPT*256; fp32 -> limbs + scale
// ---------------------------------------------------------------------------
template<int EPT>
__global__ void __launch_bounds__(256) rowquant(
    const float* __restrict__ x, int8_t* __restrict__ q0,
    int8_t* __restrict__ q1, float* __restrict__ sc, int L)
{
    const size_t base = (size_t)blockIdx.x * L;
    const int tid = threadIdx.x;
    float v[EPT];
    float m = 0.f;
    #pragma unroll
    for (int i = 0; i < EPT; i++) {
        v[i] = x[base + tid + i * 256];
        m = fmaxf(m, fabsf(v[i]));
    }
    #pragma unroll
    for (int off = 16; off; off >>= 1)
        m = fmaxf(m, __shfl_xor_sync(0xffffffffu, m, off));
    __shared__ float red[8];
    if ((tid & 31) == 0) red[tid >> 5] = m;
    __syncthreads();
    float mm = red[0];
    #pragma unroll
    for (int i = 1; i < 8; i++) mm = fmaxf(mm, red[i]);

    float inv = mm > 0.f ? 127.f / mm : 0.f;
    if (tid == 0) sc[blockIdx.x] = mm * (1.f / 127.f);
    #pragma unroll
    for (int i = 0; i < EPT; i++) {
        int8_t a, b;
        quant2(v[i], inv, a, b);
        q0[base + tid + i * 256] = a;
        q1[base + tid + i * 256] = b;
    }
}

// ---------------------------------------------------------------------------
// Column max of W[K,N] -> per-column scale (rows of W^T)
// ---------------------------------------------------------------------------
__global__ void colmax_kernel(const float* __restrict__ W, float* __restrict__ sc,
                              int K, int N)
{
    int n = blockIdx.x * 256 + threadIdx.x;
    float m = 0.f;
    for (int k = 0; k < K; k++) m = fmaxf(m, fabsf(W[(size_t)k * N + n]));
    sc[n] = m * (1.f / 127.f);
}

// ---------------------------------------------------------------------------
// Transpose-quantize: W[K,N] fp32 -> WT limbs [N,K] int8 (scale per n)
// ---------------------------------------------------------------------------
__global__ void tquant_kernel(const float* __restrict__ W,
                              const float* __restrict__ sc,
                              int8_t* __restrict__ q0, int8_t* __restrict__ q1,
                              int K, int N)
{
    __shared__ float t[32][33];
    int n0 = blockIdx.x * 32, k0 = blockIdx.y * 32;
    int x = threadIdx.x, y = threadIdx.y;
    #pragma unroll
    for (int j = 0; j < 32; j += 8)
        t[y + j][x] = W[(size_t)(k0 + y + j) * N + n0 + x];
    __syncthreads();
    #pragma unroll
    for (int j = 0; j < 32; j += 8) {
        int n = n0 + y + j;
        float s = sc[n];
        float inv = s > 0.f ? 1.f / s : 0.f;
        int8_t a, b;
        quant2(t[x][y + j], inv, a, b);
        size_t o = (size_t)n * K + k0 + x;
        q0[o] = a; q1[o] = b;
    }
}

// ---------------------------------------------------------------------------
// Row softmax over LK=2048; reads fp32 scores, writes int8 weight limbs+scale.
// max weight = exp(0) = 1, so limb0 = rint(127*exp(v-m)); scale = (1/sum)/127.
// ---------------------------------------------------------------------------
__global__ void __launch_bounds__(256) softmax_kernel(
    const float* __restrict__ S, int8_t* __restrict__ q0,
    int8_t* __restrict__ q1, float* __restrict__ sc)
{
    const float* p = S + (size_t)blockIdx.x * SLK;
    const int tid = threadIdx.x;

    float v[8];
    float mx = -1e30f;
    #pragma unroll
    for (int i = 0; i < 8; i++) { v[i] = p[tid + i * 256]; mx = fmaxf(mx, v[i]); }
    #pragma unroll
    for (int off = 16; off; off >>= 1)
        mx = fmaxf(mx, __shfl_xor_sync(0xffffffffu, mx, off));
    __shared__ float red[8];
    if ((tid & 31) == 0) red[tid >> 5] = mx;
    __syncthreads();
    float m2 = red[0];
    #pragma unroll
    for (int i = 1; i < 8; i++) m2 = fmaxf(m2, red[i]);
    __syncthreads();

    float s = 0.f;
    #pragma unroll
    for (int i = 0; i < 8; i++) { v[i] = __expf(v[i] - m2); s += v[i]; }
    #pragma unroll
    for (int off = 16; off; off >>= 1)
        s += __shfl_xor_sync(0xffffffffu, s, off);
    if ((tid & 31) == 0) red[tid >> 5] = s;
    __syncthreads();
    float tot = 0.f;
    #pragma unroll
    for (int i = 0; i < 8; i++) tot += red[i];

    if (tid == 0) sc[blockIdx.x] = (1.f / tot) * (1.f / 127.f);
    size_t base = (size_t)blockIdx.x * SLK + tid;
    #pragma unroll
    for (int i = 0; i < 8; i++) {
        int8_t a, b;
        quant2(v[i], 127.f, a, b);   // t = 127*exp in [0,127]
        q0[base + i * 256] = a;
        q1[base + i * 256] = b;
    }
}

// ---------------------------------------------------------------------------
// kernel_launch
// ---------------------------------------------------------------------------
extern "C" void kernel_launch(void* const* d_in, const int* in_sizes, int n_in,
                              void* d_out, int out_size)
{
    const float* query = (const float*)d_in[0];
    const float* key   = (const float*)d_in[1];
    const float* Wq    = (const float*)d_in[2];
    const float* bq    = (const float*)d_in[3];
    const float* Wk    = (const float*)d_in[4];
    const float* bk    = (const float*)d_in[5];
    const float* Wv    = (const float*)d_in[6];
    const float* bv    = (const float*)d_in[7];
    float* out = (float*)d_out;

    int8_t *q0,*q1,*k0,*k1,*wq0,*wq1,*wk0,*wk1,*wv0,*wv1;
    int8_t *qp0,*qp1,*kp0,*kp1,*vt0,*vt1,*w0,*w1;
    float *s_q,*s_k,*s_wq,*s_wk,*s_wv,*s_qp,*s_kp,*s_vt,*s_w,*F,*S;
    cudaGetSymbolAddress((void**)&q0,  g_q0);  cudaGetSymbolAddress((void**)&q1,  g_q1);
    cudaGetSymbolAddress((void**)&k0,  g_k0);  cudaGetSymbolAddress((void**)&k1,  g_k1);
    cudaGetSymbolAddress((void**)&wq0, g_wq0); cudaGetSymbolAddress((void**)&wq1, g_wq1);
    cudaGetSymbolAddress((void**)&wk0, g_wk0); cudaGetSymbolAddress((void**)&wk1, g_wk1);
    cudaGetSymbolAddress((void**)&wv0, g_wv0); cudaGetSymbolAddress((void**)&wv1, g_wv1);
    cudaGetSymbolAddress((void**)&qp0, g_qp0); cudaGetSymbolAddress((void**)&qp1, g_qp1);
    cudaGetSymbolAddress((void**)&kp0, g_kp0); cudaGetSymbolAddress((void**)&kp1, g_kp1);
    cudaGetSymbolAddress((void**)&vt0, g_vt0); cudaGetSymbolAddress((void**)&vt1, g_vt1);
    cudaGetSymbolAddress((void**)&w0,  g_w0);  cudaGetSymbolAddress((void**)&w1,  g_w1);
    cudaGetSymbolAddress((void**)&s_q,  g_s_q);  cudaGetSymbolAddress((void**)&s_k,  g_s_k);
    cudaGetSymbolAddress((void**)&s_wq, g_s_wq); cudaGetSymbolAddress((void**)&s_wk, g_s_wk);
    cudaGetSymbolAddress((void**)&s_wv, g_s_wv);
    cudaGetSymbolAddress((void**)&s_qp, g_s_qp); cudaGetSymbolAddress((void**)&s_kp, g_s_kp);
    cudaGetSymbolAddress((void**)&s_vt, g_s_vt); cudaGetSymbolAddress((void**)&s_w,  g_s_w);
    cudaGetSymbolAddress((void**)&F, g_F);       cudaGetSymbolAddress((void**)&S, g_S);

    cudaFuncSetAttribute(imma_gemm<0>, cudaFuncAttributeMaxDynamicSharedMemorySize, GEMM_SMEM);
    cudaFuncSetAttribute(imma_gemm<1>, cudaFuncAttributeMaxDynamicSharedMemorySize, GEMM_SMEM);
    cudaFuncSetAttribute(imma_gemm<2>, cudaFuncAttributeMaxDynamicSharedMemorySize, GEMM_SMEM);

    // 1. quantize inputs (per-row)
    rowquant<3><<<NB*SLQ, 256>>>(query, q0, q1, s_q, SDQ);
    rowquant<4><<<NB*SLK, 256>>>(key,   k0, k1, s_k, SDK);

    // 2. weight transpose-quant (per output-dim scale)
    colmax_kernel<<<SDK/256, 256>>>(Wq, s_wq, SDQ, SDK);
    colmax_kernel<<<SDK/256, 256>>>(Wk, s_wk, SDK, SDK);
    colmax_kernel<<<SDK/256, 256>>>(Wv, s_wv, SDK, SDK);
    tquant_kernel<<<dim3(SDK/32, SDQ/32), dim3(32,8)>>>(Wq, s_wq, wq0, wq1, SDQ, SDK);
    tquant_kernel<<<dim3(SDK/32, SDK/32), dim3(32,8)>>>(Wk, s_wk, wk0, wk1, SDK, SDK);
    tquant_kernel<<<dim3(SDK/32, SDK/32), dim3(32,8)>>>(Wv, s_wv, wv0, wv1, SDK, SDK);

    // 3. Q projection (M=32768, N=1024, K=768) -> F fp32 -> quant
    imma_gemm<1><<<dim3(SDK/BN, (NB*SLQ)/BM, 1), 256, GEMM_SMEM>>>(
        q0, q1, wq0, wq1, s_q, s_wq, bq, F, SDK, SDQ, 1.f, 0, 0, 0, 0, 0);
    rowquant<4><<<NB*SLQ, 256>>>(F, qp0, qp1, s_qp, SDK);

    // 4. K projection (M=32768, N=1024, K=1024) -> F -> quant
    imma_gemm<1><<<dim3(SDK/BN, (NB*SLK)/BM, 1), 256, GEMM_SMEM>>>(
        k0, k1, wk0, wk1, s_k, s_wk, bk, F, SDK, SDK, 1.f, 0, 0, 0, 0, 0);
    rowquant<4><<<NB*SLK, 256>>>(F, kp0, kp1, s_kp, SDK);

    // 5. V projection transposed: Vt[b][d][t] (M=1024, N=2048, K=1024), row bias
    imma_gemm<2><<<dim3(SLK/BN, SDK/BM, NB), 256, GEMM_SMEM>>>(
        wv0, wv1, k0, k1, s_wv, s_k, bv, F,
        SLK, SDK, 1.f, 0, (long)SLK*SDK, (long)SDK*SLK, 0, SLK);
    rowquant<8><<<NB*SDK, 256>>>(F, vt0, vt1, s_vt, SLK);

    // 6. scores = (Qp @ Kp^T)/32  (M=2048, N=2048, K=1024 per batch)
    imma_gemm<0><<<dim3(SLK/BN, SLQ/BM, NB), 256, GEMM_SMEM>>>(
        qp0, qp1, kp0, kp1, s_qp, s_kp, nullptr, S,
        SLK, SDK, 0.03125f, (long)SLQ*SDK, (long)SLK*SDK, (long)SLQ*SLK, SLQ, SLK);

    // 7. softmax -> int8 weight limbs + scales
    softmax_kernel<<<NB*SLQ, 256>>>(S, w0, w1, s_w);

    // 8. out = weights @ Vt^T  (M=2048, N=1024, K=2048 per batch)
    imma_gemm<0><<<dim3(SDK/BN, SLQ/BM, NB), 256, GEMM_SMEM>>>(
        w0, w1, vt0, vt1, s_w, s_vt, nullptr, out,
        SDK, SLK, 1.f, (long)SLQ*SLK, (long)SDK*SLK, (long)SLQ*SDK, SLQ, SDK);
}

// round 5
// speedup vs baseline: 3.1189x; 3.1189x over previous
#include <cuda_runtime.h>
#include <cuda_bf16.h>
#include <stdint.h>

typedef __nv_bfloat16 bf16;

#define NB  16
#define SLQ 2048
#define SLK 2048
#define SDQ 768
#define SDK 1024

// ---------------------------------------------------------------------------
// Device-global scratch
// ---------------------------------------------------------------------------
__device__ bf16 g_qh [(size_t)NB*SLQ*SDQ];   // split(query)
__device__ bf16 g_ql [(size_t)NB*SLQ*SDQ];
__device__ bf16 g_kh [(size_t)NB*SLK*SDK];   // split(key)
__device__ bf16 g_kl [(size_t)NB*SLK*SDK];
__device__ bf16 g_wqh[SDK*SDQ];              // Wq^T split  [1024,768]
__device__ bf16 g_wql[SDK*SDQ];
__device__ bf16 g_wkh[SDK*SDK];              // Wk^T split
__device__ bf16 g_wkl[SDK*SDK];
__device__ bf16 g_wvh[SDK*SDK];              // Wv^T split
__device__ bf16 g_wvl[SDK*SDK];
__device__ bf16 g_Qph[(size_t)NB*SLQ*SDK];   // projected Q split [B,Lq,Dk]
__device__ bf16 g_Qpl[(size_t)NB*SLQ*SDK];
__device__ bf16 g_Kph[(size_t)NB*SLK*SDK];   // projected K split [B,Lk,Dk]
__device__ bf16 g_Kpl[(size_t)NB*SLK*SDK];
__device__ bf16 g_Vth[(size_t)NB*SDK*SLK];   // projected V^T split [B,Dk,Lk]
__device__ bf16 g_Vtl[(size_t)NB*SDK*SLK];
__device__ float g_S [(size_t)NB*SLQ*SLK];   // scores fp32
__device__ bf16 g_Sh [(size_t)NB*SLQ*SLK];   // softmax weights split
__device__ bf16 g_Sl [(size_t)NB*SLQ*SLK];

// ---------------------------------------------------------------------------
// PTX helpers — baseline (non-'a') features only
// ---------------------------------------------------------------------------
__device__ __forceinline__ uint32_t smem_u32(const void* p) {
    uint32_t a;
    asm("{ .reg .u64 t; cvta.to.shared.u64 t, %1; cvt.u32.u64 %0, t; }"
        : "=r"(a) : "l"(p));
    return a;
}
__device__ __forceinline__ void cpa16(uint32_t dst, const void* src) {
    asm volatile("cp.async.cg.shared.global [%0], [%1], 16;"
                 :: "r"(dst), "l"(src) : "memory");
}
__device__ __forceinline__ void cpa_commit() {
    asm volatile("cp.async.commit_group;" ::: "memory");
}
template<int N>
__device__ __forceinline__ void cpa_wait() {
    asm volatile("cp.async.wait_group %0;" :: "n"(N) : "memory");
}
__device__ __forceinline__ void ldmx4(uint32_t* r, uint32_t addr) {
    asm volatile("ldmatrix.sync.aligned.m8n8.x4.shared.b16 {%0,%1,%2,%3}, [%4];"
                 : "=r"(r[0]), "=r"(r[1]), "=r"(r[2]), "=r"(r[3]) : "r"(addr));
}
__device__ __forceinline__ void mma16816(float* c, const uint32_t* a, const uint32_t* b) {
    asm volatile(
        "mma.sync.aligned.m16n8k16.row.col.f32.bf16.bf16.f32 "
        "{%0,%1,%2,%3}, {%4,%5,%6,%7}, {%8,%9}, {%0,%1,%2,%3};"
        : "+f"(c[0]), "+f"(c[1]), "+f"(c[2]), "+f"(c[3])
        : "r"(a[0]), "r"(a[1]), "r"(a[2]), "r"(a[3]), "r"(b[0]), "r"(b[1]));
}
__device__ __forceinline__ uint32_t sw128(uint32_t o) { return o ^ ((o >> 3) & 0x70); }

__device__ __forceinline__ uint32_t split_pack(float x, float y, uint32_t& lopack) {
    bf16 hx = __float2bfloat16(x), hy = __float2bfloat16(y);
    bf16 lx = __float2bfloat16(x - __bfloat162float(hx));
    bf16 ly = __float2bfloat16(y - __bfloat162float(hy));
    lopack = (uint32_t)__bfloat16_as_ushort(lx) | ((uint32_t)__bfloat16_as_ushort(ly) << 16);
    return (uint32_t)__bfloat16_as_ushort(hx) | ((uint32_t)__bfloat16_as_ushort(hy) << 16);
}

// ---------------------------------------------------------------------------
// bf16x3 HMMA GEMM:  D[M,N] = alpha * (A @ B^T) (+ bias)
//   A hi/lo [M,K] K-major; B hi/lo [N,K] K-major.
//   CTA 128x256, BK=64 (128B rows, SW128), 2-stage cp.async, 8 warps (2m x 4n),
//   warp tile 64x64, mma.m16n8k16, 3 pass-major MMA sweeps into one accumulator.
// OUTMODE: 0 = fp32 C;  1 = split bf16 (Chi, Clo)
// BIASMODE: 0 = none; 1 = bias per column; 2 = bias per row
// ---------------------------------------------------------------------------
#define BM 128
#define BN 256
#define BKC 64
#define OFF_AL 16384
#define OFF_BH 32768
#define OFF_BL 65536
#define STAGE  98304
#define GEMM_SMEM (2*STAGE)   // 196608

template<int OUTMODE, int BIASMODE>
__global__ void __launch_bounds__(256, 1) mma_gemm(
    const bf16* __restrict__ Ah, const bf16* __restrict__ Al,
    const bf16* __restrict__ Bh, const bf16* __restrict__ Bl,
    const float* __restrict__ bias,
    float* __restrict__ Cf, bf16* __restrict__ Chi, bf16* __restrict__ Clo,
    int N, int K, float alpha,
    long batchA, long batchB, long batchC)
{
    extern __shared__ char smem[];
    const uint32_t sbase = smem_u32(smem);
    const int tid  = threadIdx.x;
    const int lane = tid & 31;
    const int wid  = tid >> 5;
    const int wm   = wid >> 2;   // 0..1  (m64)
    const int wn   = wid & 3;    // 0..3  (n64)
    const int row0 = blockIdx.y * BM;
    const int col0 = blockIdx.x * BN;
    const size_t zA = (size_t)blockIdx.z * batchA;
    const size_t zB = (size_t)blockIdx.z * batchB;
    const size_t zC = (size_t)blockIdx.z * batchC;

    const int r8 = tid >> 3;              // 0..31
    const uint32_t cb = (tid & 7) * 16;   // byte offset within 128B row

    auto load_stage = [&](int s, int k0) {
        const uint32_t st = sbase + s * STAGE;
        #pragma unroll
        for (int i = 0; i < 4; i++) {                 // A: 128 rows
            int r = r8 + i * 32;
            size_t go = (size_t)(row0 + r) * K + k0;
            uint32_t so = sw128((uint32_t)(r * 128) + cb);
            cpa16(st + so,          (const char*)(Ah + zA + go) + cb);
            cpa16(st + OFF_AL + so, (const char*)(Al + zA + go) + cb);
        }
        #pragma unroll
        for (int i = 0; i < 8; i++) {                 // B: 256 rows
            int r = r8 + i * 32;
            size_t go = (size_t)(col0 + r) * K + k0;
            uint32_t so = sw128((uint32_t)(r * 128) + cb);
            cpa16(st + OFF_BH + so, (const char*)(Bh + zB + go) + cb);
            cpa16(st + OFF_BL + so, (const char*)(Bl + zB + go) + cb);
        }
        cpa_commit();
    };

    float c[4][8][4];
    #pragma unroll
    for (int i = 0; i < 4; i++)
        #pragma unroll
        for (int j = 0; j < 8; j++)
            #pragma unroll
            for (int k = 0; k < 4; k++) c[i][j][k] = 0.f;

    const int nk = K / BKC;
    load_stage(0, 0);
    load_stage(1, BKC);

    // per-lane ldmatrix address components
    const int a_r = ((lane >> 3) & 1) * 8 + (lane & 7);
    const int a_k = ((lane >> 4) & 1) * 16;
    const int b_r = ((lane >> 4) & 1) * 8 + (lane & 7);
    const int b_k = ((lane >> 3) & 1) * 16;

    for (int i = 0; i < nk; i++) {
        if (i + 1 < nk) cpa_wait<1>(); else cpa_wait<0>();
        __syncthreads();

        const uint32_t st = sbase + (i & 1) * STAGE;
        #pragma unroll
        for (int ks = 0; ks < 4; ks++) {
            uint32_t ah[4][4], al[4][4];
            #pragma unroll
            for (int fm = 0; fm < 4; fm++) {
                int row = wm * 64 + fm * 16 + a_r;
                uint32_t so = sw128((uint32_t)(row * 128) + ks * 32 + a_k);
                ldmx4(ah[fm], st + so);
                ldmx4(al[fm], st + OFF_AL + so);
            }
            uint32_t bh_[4][4], bl_[4][4];
            #pragma unroll
            for (int g = 0; g < 4; g++) {
                int row = wn * 64 + g * 16 + b_r;
                uint32_t so = sw128((uint32_t)(row * 128) + ks * 32 + b_k);
                ldmx4(bh_[g], st + OFF_BH + so);
                ldmx4(bl_[g], st + OFF_BL + so);
            }
            // pass-major sweeps: long independent chains between same-acc MMAs
            #pragma unroll
            for (int fm = 0; fm < 4; fm++)
                #pragma unroll
                for (int fn = 0; fn < 8; fn++)
                    mma16816(c[fm][fn], ah[fm], &bh_[fn >> 1][(fn & 1) * 2]);
            #pragma unroll
            for (int fm = 0; fm < 4; fm++)
                #pragma unroll
                for (int fn = 0; fn < 8; fn++)
                    mma16816(c[fm][fn], ah[fm], &bl_[fn >> 1][(fn & 1) * 2]);
            #pragma unroll
            for (int fm = 0; fm < 4; fm++)
                #pragma unroll
                for (int fn = 0; fn < 8; fn++)
                    mma16816(c[fm][fn], al[fm], &bh_[fn >> 1][(fn & 1) * 2]);
        }
        if (i + 2 < nk) {
            __syncthreads();               // all warps done reading buf (i&1)
            load_stage(i & 1, (i + 2) * BKC);
        }
    }

    // ---- epilogue: fragments -> global ---------------------------------
    #pragma unroll
    for (int fm = 0; fm < 4; fm++)
        #pragma unroll
        for (int fn = 0; fn < 8; fn++) {
            int row = row0 + wm * 64 + fm * 16 + (lane >> 2);
            int col = col0 + wn * 64 + fn * 8 + (lane & 3) * 2;
            float v0 = c[fm][fn][0] * alpha, v1 = c[fm][fn][1] * alpha;
            float v2 = c[fm][fn][2] * alpha, v3 = c[fm][fn][3] * alpha;
            if (BIASMODE == 1) {
                float b0 = bias[col], b1 = bias[col + 1];
                v0 += b0; v1 += b1; v2 += b0; v3 += b1;
            }
            if (BIASMODE == 2) {
                float rb0 = bias[row], rb1 = bias[row + 8];
                v0 += rb0; v1 += rb0; v2 += rb1; v3 += rb1;
            }
            size_t o0 = zC + (size_t)row * N + col;
            size_t o1 = o0 + (size_t)8 * N;
            if (OUTMODE == 0) {
                *(float2*)(Cf + o0) = make_float2(v0, v1);
                *(float2*)(Cf + o1) = make_float2(v2, v3);
            } else {
                uint32_t lo0, lo1;
                uint32_t hi0 = split_pack(v0, v1, lo0);
                uint32_t hi1 = split_pack(v2, v3, lo1);
                *(uint32_t*)(Chi + o0) = hi0;
                *(uint32_t*)(Clo + o0) = lo0;
                *(uint32_t*)(Chi + o1) = hi1;
                *(uint32_t*)(Clo + o1) = lo1;
            }
        }
}

// ---------------------------------------------------------------------------
// Elementwise split: fp32 -> (hi, lo) bf16.  n multiple of 4.
// ---------------------------------------------------------------------------
__global__ void split_kernel(const float* __restrict__ x,
                             bf16* __restrict__ hi, bf16* __restrict__ lo, size_t n)
{
    size_t i = ((size_t)blockIdx.x * blockDim.x + threadIdx.x) * 4;
    if (i >= n) return;
    float4 v = *(const float4*)(x + i);
    uint32_t l0, l1;
    uint32_t h0 = split_pack(v.x, v.y, l0);
    uint32_t h1 = split_pack(v.z, v.w, l1);
    *(uint2*)(hi + i) = make_uint2(h0, h1);
    *(uint2*)(lo + i) = make_uint2(l0, l1);
}

// ---------------------------------------------------------------------------
// Transposed split: W [K,N] fp32 -> Wt hi/lo [N,K] bf16.
// ---------------------------------------------------------------------------
__global__ void transpose_split_kernel(const float* __restrict__ W,
                                       bf16* __restrict__ hi, bf16* __restrict__ lo,
                                       int K, int N)
{
    __shared__ float t[32][33];
    int n0 = blockIdx.x * 32, k0 = blockIdx.y * 32;
    int x = threadIdx.x, y = threadIdx.y;
    #pragma unroll
    for (int j = 0; j < 32; j += 8)
        t[y + j][x] = W[(size_t)(k0 + y + j) * N + n0 + x];
    __syncthreads();
    #pragma unroll
    for (int j = 0; j < 32; j += 8) {
        float v = t[x][y + j];
        bf16 h = __float2bfloat16(v);
        bf16 l = __float2bfloat16(v - __bfloat162float(h));
        size_t o = (size_t)(n0 + y + j) * K + k0 + x;
        hi[o] = h; lo[o] = l;
    }
}

// ---------------------------------------------------------------------------
// Row softmax over LK=2048; reads fp32, writes split bf16 weights.
// ---------------------------------------------------------------------------
__global__ void __launch_bounds__(256) softmax_kernel(
    const float* __restrict__ S, bf16* __restrict__ Sh, bf16* __restrict__ Sl)
{
    const float* p = S + (size_t)blockIdx.x * SLK;
    const int tid = threadIdx.x;

    float v[8];
    float mx = -1e30f;
    #pragma unroll
    for (int i = 0; i < 8; i++) { v[i] = p[tid + i * 256]; mx = fmaxf(mx, v[i]); }
    #pragma unroll
    for (int off = 16; off; off >>= 1)
        mx = fmaxf(mx, __shfl_xor_sync(0xffffffffu, mx, off));

    __shared__ float red[8];
    if ((tid & 31) == 0) red[tid >> 5] = mx;
    __syncthreads();
    float m2 = red[0];
    #pragma unroll
    for (int i = 1; i < 8; i++) m2 = fmaxf(m2, red[i]);
    __syncthreads();

    float s = 0.f;
    #pragma unroll
    for (int i = 0; i < 8; i++) { v[i] = __expf(v[i] - m2); s += v[i]; }
    #pragma unroll
    for (int off = 16; off; off >>= 1)
        s += __shfl_xor_sync(0xffffffffu, s, off);
    if ((tid & 31) == 0) red[tid >> 5] = s;
    __syncthreads();
    float tot = 0.f;
    #pragma unroll
    for (int i = 0; i < 8; i++) tot += red[i];

    float inv = 1.f / tot;
    size_t base = (size_t)blockIdx.x * SLK + tid;
    #pragma unroll
    for (int i = 0; i < 8; i++) {
        float w = v[i] * inv;
        bf16 h = __float2bfloat16(w);
        bf16 l = __float2bfloat16(w - __bfloat162float(h));
        Sh[base + i * 256] = h;
        Sl[base + i * 256] = l;
    }
}

// ---------------------------------------------------------------------------
// kernel_launch
// ---------------------------------------------------------------------------
extern "C" void kernel_launch(void* const* d_in, const int* in_sizes, int n_in,
                              void* d_out, int out_size)
{
    const float* query = (const float*)d_in[0];
    const float* key   = (const float*)d_in[1];
    const float* Wq    = (const float*)d_in[2];
    const float* bq    = (const float*)d_in[3];
    const float* Wk    = (const float*)d_in[4];
    const float* bk    = (const float*)d_in[5];
    const float* Wv    = (const float*)d_in[6];
    const float* bv    = (const float*)d_in[7];
    float* out = (float*)d_out;

    bf16 *qh,*ql,*kh,*kl,*wqh,*wql,*wkh,*wkl,*wvh,*wvl;
    bf16 *Qph,*Qpl,*Kph,*Kpl,*Vth,*Vtl,*Sh,*Sl;
    float *S;
    cudaGetSymbolAddress((void**)&qh,  g_qh);  cudaGetSymbolAddress((void**)&ql,  g_ql);
    cudaGetSymbolAddress((void**)&kh,  g_kh);  cudaGetSymbolAddress((void**)&kl,  g_kl);
    cudaGetSymbolAddress((void**)&wqh, g_wqh); cudaGetSymbolAddress((void**)&wql, g_wql);
    cudaGetSymbolAddress((void**)&wkh, g_wkh); cudaGetSymbolAddress((void**)&wkl, g_wkl);
    cudaGetSymbolAddress((void**)&wvh, g_wvh); cudaGetSymbolAddress((void**)&wvl, g_wvl);
    cudaGetSymbolAddress((void**)&Qph, g_Qph); cudaGetSymbolAddress((void**)&Qpl, g_Qpl);
    cudaGetSymbolAddress((void**)&Kph, g_Kph); cudaGetSymbolAddress((void**)&Kpl, g_Kpl);
    cudaGetSymbolAddress((void**)&Vth, g_Vth); cudaGetSymbolAddress((void**)&Vtl, g_Vtl);
    cudaGetSymbolAddress((void**)&S,   g_S);
    cudaGetSymbolAddress((void**)&Sh,  g_Sh);  cudaGetSymbolAddress((void**)&Sl,  g_Sl);

    cudaFuncSetAttribute(mma_gemm<0,0>, cudaFuncAttributeMaxDynamicSharedMemorySize, GEMM_SMEM);
    cudaFuncSetAttribute(mma_gemm<1,1>, cudaFuncAttributeMaxDynamicSharedMemorySize, GEMM_SMEM);
    cudaFuncSetAttribute(mma_gemm<1,2>, cudaFuncAttributeMaxDynamicSharedMemorySize, GEMM_SMEM);

    // 1. split inputs
    {
        size_t nq = (size_t)NB * SLQ * SDQ;
        split_kernel<<<(unsigned)((nq/4 + 255)/256), 256>>>(query, qh, ql, nq);
        size_t nkk = (size_t)NB * SLK * SDK;
        split_kernel<<<(unsigned)((nkk/4 + 255)/256), 256>>>(key, kh, kl, nkk);
    }
    // 2. transpose-split weights (W[K,N] -> Wt[N,K])
    transpose_split_kernel<<<dim3(SDK/32, SDQ/32), dim3(32,8)>>>(Wq, wqh, wql, SDQ, SDK);
    transpose_split_kernel<<<dim3(SDK/32, SDK/32), dim3(32,8)>>>(Wk, wkh, wkl, SDK, SDK);
    transpose_split_kernel<<<dim3(SDK/32, SDK/32), dim3(32,8)>>>(Wv, wvh, wvl, SDK, SDK);

    // 3. Q projection (M=B*Lq=32768, N=1024, K=768)
    mma_gemm<1,1><<<dim3(SDK/BN, (NB*SLQ)/BM, 1), 256, GEMM_SMEM>>>(
        qh, ql, wqh, wql, bq, nullptr, Qph, Qpl,
        SDK, SDQ, 1.f, 0, 0, 0);

    // 4. K projection (M=32768, N=1024, K=1024)
    mma_gemm<1,1><<<dim3(SDK/BN, (NB*SLK)/BM, 1), 256, GEMM_SMEM>>>(
        kh, kl, wkh, wkl, bk, nullptr, Kph, Kpl,
        SDK, SDK, 1.f, 0, 0, 0);

    // 5. V projection, transposed output: VpT[b][o][t] (M=1024, N=2048, K=1024)
    mma_gemm<1,2><<<dim3(SLK/BN, SDK/BM, NB), 256, GEMM_SMEM>>>(
        wvh, wvl, kh, kl, bv, nullptr, Vth, Vtl,
        SLK, SDK, 1.f, 0, (long)SLK*SDK, (long)SDK*SLK);

    // 6. scores = (Qp @ Kp^T) / 32  (M=2048, N=2048, K=1024 per batch)
    mma_gemm<0,0><<<dim3(SLK/BN, SLQ/BM, NB), 256, GEMM_SMEM>>>(
        Qph, Qpl, Kph, Kpl, nullptr, S, nullptr, nullptr,
        SLK, SDK, 0.03125f, (long)SLQ*SDK, (long)SLK*SDK, (long)SLQ*SLK);

    // 7. softmax -> split weights
    softmax_kernel<<<NB*SLQ, 256>>>(S, Sh, Sl);

    // 8. out = weights @ Vp  (M=2048, N=1024, K=2048 per batch)
    mma_gemm<0,0><<<dim3(SDK/BN, SLQ/BM, NB), 256, GEMM_SMEM>>>(
        Sh, Sl, Vth, Vtl, nullptr, out, nullptr, nullptr,
        SDK, SLK, 1.f, (long)SLQ*SLK, (long)SDK*SLK, (long)SLQ*SDK);
}

// round 6
// speedup vs baseline: 3.9403x; 1.2634x over previous
#include <cuda_runtime.h>
#include <cuda_fp16.h>
#include <stdint.h>

#define NB  16
#define SLQ 2048
#define SLK 2048
#define SDQ 768
#define SDK 1024

// ---------------------------------------------------------------------------
// Device-global scratch (fp16 limb pairs: x ~= hi + lo, lo = fp16(x-hi))
// ---------------------------------------------------------------------------
__device__ __half g_qh [(size_t)NB*SLQ*SDQ];   // split(query)
__device__ __half g_ql [(size_t)NB*SLQ*SDQ];
__device__ __half g_kh [(size_t)NB*SLK*SDK];   // split(key)
__device__ __half g_kl [(size_t)NB*SLK*SDK];
__device__ __half g_wqh[SDK*SDQ];              // Wq^T hi  [1024,768]
__device__ __half g_wkh[SDK*SDK];              // Wk^T hi
__device__ __half g_wvh[SDK*SDK];              // Wv^T split (A of V proj)
__device__ __half g_wvl[SDK*SDK];
__device__ __half g_Qph[(size_t)NB*SLQ*SDK];   // projected Q split
__device__ __half g_Qpl[(size_t)NB*SLQ*SDK];
__device__ __half g_Kph[(size_t)NB*SLK*SDK];   // projected K hi only
__device__ __half g_Vth[(size_t)NB*SDK*SLK];   // projected V^T split [B,Dk,Lk]
__device__ __half g_Vtl[(size_t)NB*SDK*SLK];
__device__ float  g_S [(size_t)NB*SLQ*SLK];    // scores fp32
__device__ __half g_Sh [(size_t)NB*SLQ*SLK];   // softmax weights split
__device__ __half g_Sl [(size_t)NB*SLQ*SLK];

// ---------------------------------------------------------------------------
// PTX helpers — baseline (non-'a') features only
// ---------------------------------------------------------------------------
__device__ __forceinline__ uint32_t smem_u32(const void* p) {
    uint32_t a;
    asm("{ .reg .u64 t; cvta.to.shared.u64 t, %1; cvt.u32.u64 %0, t; }"
        : "=r"(a) : "l"(p));
    return a;
}
__device__ __forceinline__ void cpa16(uint32_t dst, const void* src) {
    asm volatile("cp.async.cg.shared.global [%0], [%1], 16;"
                 :: "r"(dst), "l"(src) : "memory");
}
__device__ __forceinline__ void cpa_commit() {
    asm volatile("cp.async.commit_group;" ::: "memory");
}
template<int N>
__device__ __forceinline__ void cpa_wait() {
    asm volatile("cp.async.wait_group %0;" :: "n"(N) : "memory");
}
__device__ __forceinline__ void ldmx4(uint32_t* r, uint32_t addr) {
    asm volatile("ldmatrix.sync.aligned.m8n8.x4.shared.b16 {%0,%1,%2,%3}, [%4];"
                 : "=r"(r[0]), "=r"(r[1]), "=r"(r[2]), "=r"(r[3]) : "r"(addr));
}
__device__ __forceinline__ void mma16816(float* c, const uint32_t* a, const uint32_t* b) {
    asm volatile(
        "mma.sync.aligned.m16n8k16.row.col.f32.f16.f16.f32 "
        "{%0,%1,%2,%3}, {%4,%5,%6,%7}, {%8,%9}, {%0,%1,%2,%3};"
        : "+f"(c[0]), "+f"(c[1]), "+f"(c[2]), "+f"(c[3])
        : "r"(a[0]), "r"(a[1]), "r"(a[2]), "r"(a[3]), "r"(b[0]), "r"(b[1]));
}
__device__ __forceinline__ uint32_t sw128(uint32_t o) { return o ^ ((o >> 3) & 0x70); }

__device__ __forceinline__ uint32_t hsplit_pack(float x, float y, uint32_t& lopack) {
    __half hx = __float2half_rn(x), hy = __float2half_rn(y);
    __half lx = __float2half_rn(x - __half2float(hx));
    __half ly = __float2half_rn(y - __half2float(hy));
    lopack = (uint32_t)__half_as_ushort(lx) | ((uint32_t)__half_as_ushort(ly) << 16);
    return (uint32_t)__half_as_ushort(hx) | ((uint32_t)__half_as_ushort(hy) << 16);
}

// ---------------------------------------------------------------------------
// fp16 multi-pass HMMA GEMM:  D[M,N] = alpha * (A @ B^T) (+ bias)
//   A hi/lo [M,K] K-major; B hi (+lo if NPASS=3) [N,K] K-major.
//   CTA 128x256, BK=64 (128B rows, SW128), 2-stage cp.async, 8 warps (2m x 4n),
//   warp tile 64x64, mma.m16n8k16.
//   NPASS=2: AhBh + AlBh (B fp16-rounded).  NPASS=3: + AhBl.
// OUTMODE: 0 = fp32; 1 = split fp16 (Chi,Clo); 2 = fp16 hi only
// BIASMODE: 0 = none; 1 = per column; 2 = per row
// ---------------------------------------------------------------------------
#define BM 128
#define BN 256
#define BKC 64

template<int NPASS, int OUTMODE, int BIASMODE>
__global__ void __launch_bounds__(256, 1) mma_gemm(
    const __half* __restrict__ Ah, const __half* __restrict__ Al,
    const __half* __restrict__ Bh, const __half* __restrict__ Bl,
    const float* __restrict__ bias,
    float* __restrict__ Cf, __half* __restrict__ Chi, __half* __restrict__ Clo,
    int N, int K, float alpha,
    long batchA, long batchB, long batchC)
{
    constexpr uint32_t OFF_AL = 16384;
    constexpr uint32_t OFF_BH = 32768;
    constexpr uint32_t OFF_BL = 65536;
    constexpr uint32_t STAGE  = (NPASS == 3) ? 98304u : 65536u;

    extern __shared__ char smem[];
    const uint32_t sbase = smem_u32(smem);
    const int tid  = threadIdx.x;
    const int lane = tid & 31;
    const int wid  = tid >> 5;
    const int wm   = wid >> 2;   // 0..1  (m64)
    const int wn   = wid & 3;    // 0..3  (n64)
    const int row0 = blockIdx.y * BM;
    const int col0 = blockIdx.x * BN;
    const size_t zA = (size_t)blockIdx.z * batchA;
    const size_t zB = (size_t)blockIdx.z * batchB;
    const size_t zC = (size_t)blockIdx.z * batchC;

    const int r8 = tid >> 3;              // 0..31
    const uint32_t cb = (tid & 7) * 16;   // byte offset within 128B row

    auto load_stage = [&](int s, int k0) {
        const uint32_t st = sbase + s * STAGE;
        #pragma unroll
        for (int i = 0; i < 4; i++) {                 // A: 128 rows, 2 limbs
            int r = r8 + i * 32;
            size_t go = (size_t)(row0 + r) * K + k0;
            uint32_t so = sw128((uint32_t)(r * 128) + cb);
            cpa16(st + so,          (const char*)(Ah + zA + go) + cb);
            cpa16(st + OFF_AL + so, (const char*)(Al + zA + go) + cb);
        }
        #pragma unroll
        for (int i = 0; i < 8; i++) {                 // B: 256 rows
            int r = r8 + i * 32;
            size_t go = (size_t)(col0 + r) * K + k0;
            uint32_t so = sw128((uint32_t)(r * 128) + cb);
            cpa16(st + OFF_BH + so, (const char*)(Bh + zB + go) + cb);
            if (NPASS == 3)
                cpa16(st + OFF_BL + so, (const char*)(Bl + zB + go) + cb);
        }
        cpa_commit();
    };

    float c[4][8][4];
    #pragma unroll
    for (int i = 0; i < 4; i++)
        #pragma unroll
        for (int j = 0; j < 8; j++)
            #pragma unroll
            for (int k = 0; k < 4; k++) c[i][j][k] = 0.f;

    const int nk = K / BKC;
    load_stage(0, 0);
    load_stage(1, BKC);

    const int a_r = ((lane >> 3) & 1) * 8 + (lane & 7);
    const int a_k = ((lane >> 4) & 1) * 16;
    const int b_r = ((lane >> 4) & 1) * 8 + (lane & 7);
    const int b_k = ((lane >> 3) & 1) * 16;

    for (int i = 0; i < nk; i++) {
        if (i + 1 < nk) cpa_wait<1>(); else cpa_wait<0>();
        __syncthreads();

        const uint32_t st = sbase + (i & 1) * STAGE;
        #pragma unroll
        for (int ks = 0; ks < 4; ks++) {
            uint32_t ah[4][4], al[4][4];
            #pragma unroll
            for (int fm = 0; fm < 4; fm++) {
                int row = wm * 64 + fm * 16 + a_r;
                uint32_t so = sw128((uint32_t)(row * 128) + ks * 32 + a_k);
                ldmx4(ah[fm], st + so);
                ldmx4(al[fm], st + OFF_AL + so);
            }
            uint32_t bh_[4][4];
            #pragma unroll
            for (int g = 0; g < 4; g++) {
                int row = wn * 64 + g * 16 + b_r;
                uint32_t so = sw128((uint32_t)(row * 128) + ks * 32 + b_k);
                ldmx4(bh_[g], st + OFF_BH + so);
            }
            #pragma unroll
            for (int fm = 0; fm < 4; fm++)
                #pragma unroll
                for (int fn = 0; fn < 8; fn++)
                    mma16816(c[fm][fn], ah[fm], &bh_[fn >> 1][(fn & 1) * 2]);
            if (NPASS == 3) {
                uint32_t bl_[4][4];
                #pragma unroll
                for (int g = 0; g < 4; g++) {
                    int row = wn * 64 + g * 16 + b_r;
                    uint32_t so = sw128((uint32_t)(row * 128) + ks * 32 + b_k);
                    ldmx4(bl_[g], st + OFF_BL + so);
                }
                #pragma unroll
                for (int fm = 0; fm < 4; fm++)
                    #pragma unroll
                    for (int fn = 0; fn < 8; fn++)
                        mma16816(c[fm][fn], ah[fm], &bl_[fn >> 1][(fn & 1) * 2]);
            }
            #pragma unroll
            for (int fm = 0; fm < 4; fm++)
                #pragma unroll
                for (int fn = 0; fn < 8; fn++)
                    mma16816(c[fm][fn], al[fm], &bh_[fn >> 1][(fn & 1) * 2]);
        }
        if (i + 2 < nk) {
            __syncthreads();
            load_stage(i & 1, (i + 2) * BKC);
        }
    }

    // ---- epilogue -------------------------------------------------------
    #pragma unroll
    for (int fm = 0; fm < 4; fm++)
        #pragma unroll
        for (int fn = 0; fn < 8; fn++) {
            int row = row0 + wm * 64 + fm * 16 + (lane >> 2);
            int col = col0 + wn * 64 + fn * 8 + (lane & 3) * 2;
            float v0 = c[fm][fn][0] * alpha, v1 = c[fm][fn][1] * alpha;
            float v2 = c[fm][fn][2] * alpha, v3 = c[fm][fn][3] * alpha;
            if (BIASMODE == 1) {
                float b0 = bias[col], b1 = bias[col + 1];
                v0 += b0; v1 += b1; v2 += b0; v3 += b1;
            }
            if (BIASMODE == 2) {
                float rb0 = bias[row], rb1 = bias[row + 8];
                v0 += rb0; v1 += rb0; v2 += rb1; v3 += rb1;
            }
            size_t o0 = zC + (size_t)row * N + col;
            size_t o1 = o0 + (size_t)8 * N;
            if (OUTMODE == 0) {
                *(float2*)(Cf + o0) = make_float2(v0, v1);
                *(float2*)(Cf + o1) = make_float2(v2, v3);
            } else if (OUTMODE == 1) {
                uint32_t lo0, lo1;
                uint32_t hi0 = hsplit_pack(v0, v1, lo0);
                uint32_t hi1 = hsplit_pack(v2, v3, lo1);
                *(uint32_t*)(Chi + o0) = hi0;
                *(uint32_t*)(Clo + o0) = lo0;
                *(uint32_t*)(Chi + o1) = hi1;
                *(uint32_t*)(Clo + o1) = lo1;
            } else {
                uint32_t dmy0, dmy1;
                uint32_t hi0 = hsplit_pack(v0, v1, dmy0);
                uint32_t hi1 = hsplit_pack(v2, v3, dmy1);
                *(uint32_t*)(Chi + o0) = hi0;
                *(uint32_t*)(Chi + o1) = hi1;
            }
        }
}

// ---------------------------------------------------------------------------
// Elementwise split: fp32 -> (hi, lo) fp16.  n multiple of 4.
// ---------------------------------------------------------------------------
__global__ void split_kernel(const float* __restrict__ x,
                             __half* __restrict__ hi, __half* __restrict__ lo, size_t n)
{
    size_t i = ((size_t)blockIdx.x * blockDim.x + threadIdx.x) * 4;
    if (i >= n) return;
    float4 v = *(const float4*)(x + i);
    uint32_t l0, l1;
    uint32_t h0 = hsplit_pack(v.x, v.y, l0);
    uint32_t h1 = hsplit_pack(v.z, v.w, l1);
    *(uint2*)(hi + i) = make_uint2(h0, h1);
    *(uint2*)(lo + i) = make_uint2(l0, l1);
}

// ---------------------------------------------------------------------------
// Transposed split: W [K,N] fp32 -> Wt [N,K] fp16 (hi always, lo if WANTLO)
// ---------------------------------------------------------------------------
template<bool WANTLO>
__global__ void transpose_split_kernel(const float* __restrict__ W,
                                       __half* __restrict__ hi, __half* __restrict__ lo,
                                       int K, int N)
{
    __shared__ float t[32][33];
    int n0 = blockIdx.x * 32, k0 = blockIdx.y * 32;
    int x = threadIdx.x, y = threadIdx.y;
    #pragma unroll
    for (int j = 0; j < 32; j += 8)
        t[y + j][x] = W[(size_t)(k0 + y + j) * N + n0 + x];
    __syncthreads();
    #pragma unroll
    for (int j = 0; j < 32; j += 8) {
        float v = t[x][y + j];
        __half h = __float2half_rn(v);
        size_t o = (size_t)(n0 + y + j) * K + k0 + x;
        hi[o] = h;
        if (WANTLO) lo[o] = __float2half_rn(v - __half2float(h));
    }
}

// ---------------------------------------------------------------------------
// Row softmax over LK=2048; reads fp32, writes split fp16 weights.
// ---------------------------------------------------------------------------
__global__ void __launch_bounds__(256) softmax_kernel(
    const float* __restrict__ S, __half* __restrict__ Sh, __half* __restrict__ Sl)
{
    const float* p = S + (size_t)blockIdx.x * SLK;
    const int tid = threadIdx.x;

    float v[8];
    float mx = -1e30f;
    #pragma unroll
    for (int i = 0; i < 8; i++) { v[i] = p[tid + i * 256]; mx = fmaxf(mx, v[i]); }
    #pragma unroll
    for (int off = 16; off; off >>= 1)
        mx = fmaxf(mx, __shfl_xor_sync(0xffffffffu, mx, off));

    __shared__ float red[8];
    if ((tid & 31) == 0) red[tid >> 5] = mx;
    __syncthreads();
    float m2 = red[0];
    #pragma unroll
    for (int i = 1; i < 8; i++) m2 = fmaxf(m2, red[i]);
    __syncthreads();

    float s = 0.f;
    #pragma unroll
    for (int i = 0; i < 8; i++) { v[i] = __expf(v[i] - m2); s += v[i]; }
    #pragma unroll
    for (int off = 16; off; off >>= 1)
        s += __shfl_xor_sync(0xffffffffu, s, off);
    if ((tid & 31) == 0) red[tid >> 5] = s;
    __syncthreads();
    float tot = 0.f;
    #pragma unroll
    for (int i = 0; i < 8; i++) tot += red[i];

    float inv = 1.f / tot;
    size_t base = (size_t)blockIdx.x * SLK + tid;
    #pragma unroll
    for (int i = 0; i < 8; i++) {
        float w = v[i] * inv;
        __half h = __float2half_rn(w);
        Sh[base + i * 256] = h;
        Sl[base + i * 256] = __float2half_rn(w - __half2float(h));
    }
}

// ---------------------------------------------------------------------------
// kernel_launch
// ---------------------------------------------------------------------------
extern "C" void kernel_launch(void* const* d_in, const int* in_sizes, int n_in,
                              void* d_out, int out_size)
{
    const float* query = (const float*)d_in[0];
    const float* key   = (const float*)d_in[1];
    const float* Wq    = (const float*)d_in[2];
    const float* bq    = (const float*)d_in[3];
    const float* Wk    = (const float*)d_in[4];
    const float* bk    = (const float*)d_in[5];
    const float* Wv    = (const float*)d_in[6];
    const float* bv    = (const float*)d_in[7];
    float* out = (float*)d_out;

    __half *qh,*ql,*kh,*kl,*wqh,*wkh,*wvh,*wvl;
    __half *Qph,*Qpl,*Kph,*Vth,*Vtl,*Sh,*Sl;
    float *S;
    cudaGetSymbolAddress((void**)&qh,  g_qh);  cudaGetSymbolAddress((void**)&ql,  g_ql);
    cudaGetSymbolAddress((void**)&kh,  g_kh);  cudaGetSymbolAddress((void**)&kl,  g_kl);
    cudaGetSymbolAddress((void**)&wqh, g_wqh);
    cudaGetSymbolAddress((void**)&wkh, g_wkh);
    cudaGetSymbolAddress((void**)&wvh, g_wvh); cudaGetSymbolAddress((void**)&wvl, g_wvl);
    cudaGetSymbolAddress((void**)&Qph, g_Qph); cudaGetSymbolAddress((void**)&Qpl, g_Qpl);
    cudaGetSymbolAddress((void**)&Kph, g_Kph);
    cudaGetSymbolAddress((void**)&Vth, g_Vth); cudaGetSymbolAddress((void**)&Vtl, g_Vtl);
    cudaGetSymbolAddress((void**)&S,   g_S);
    cudaGetSymbolAddress((void**)&Sh,  g_Sh);  cudaGetSymbolAddress((void**)&Sl,  g_Sl);

    const int SM2 = 131072;   // 2-pass: 2 stages x 64KB
    const int SM3 = 196608;   // 3-pass: 2 stages x 96KB
    cudaFuncSetAttribute(mma_gemm<2,1,1>, cudaFuncAttributeMaxDynamicSharedMemorySize, SM2);
    cudaFuncSetAttribute(mma_gemm<2,2,1>, cudaFuncAttributeMaxDynamicSharedMemorySize, SM2);
    cudaFuncSetAttribute(mma_gemm<2,1,2>, cudaFuncAttributeMaxDynamicSharedMemorySize, SM2);
    cudaFuncSetAttribute(mma_gemm<2,0,0>, cudaFuncAttributeMaxDynamicSharedMemorySize, SM2);
    cudaFuncSetAttribute(mma_gemm<3,0,0>, cudaFuncAttributeMaxDynamicSharedMemorySize, SM3);

    // 1. split inputs (2 fp16 limbs)
    {
        size_t nq = (size_t)NB * SLQ * SDQ;
        split_kernel<<<(unsigned)((nq/4 + 255)/256), 256>>>(query, qh, ql, nq);
        size_t nkk = (size_t)NB * SLK * SDK;
        split_kernel<<<(unsigned)((nkk/4 + 255)/256), 256>>>(key, kh, kl, nkk);
    }
    // 2. transpose weights: Wq/Wk hi-only (B of 2-pass GEMMs), Wv 2 limbs (A of V proj)
    transpose_split_kernel<false><<<dim3(SDK/32, SDQ/32), dim3(32,8)>>>(Wq, wqh, nullptr, SDQ, SDK);
    transpose_split_kernel<false><<<dim3(SDK/32, SDK/32), dim3(32,8)>>>(Wk, wkh, nullptr, SDK, SDK);
    transpose_split_kernel<true ><<<dim3(SDK/32, SDK/32), dim3(32,8)>>>(Wv, wvh, wvl, SDK, SDK);

    // 3. Q projection (M=32768, N=1024, K=768), 2-pass, split output
    mma_gemm<2,1,1><<<dim3(SDK/BN, (NB*SLQ)/BM, 1), 256, SM2>>>(
        qh, ql, wqh, nullptr, bq, nullptr, Qph, Qpl,
        SDK, SDQ, 1.f, 0, 0, 0);

    // 4. K projection (M=32768, N=1024, K=1024), 2-pass, hi-only output
    mma_gemm<2,2,1><<<dim3(SDK/BN, (NB*SLK)/BM, 1), 256, SM2>>>(
        kh, kl, wkh, nullptr, bk, nullptr, Kph, nullptr,
        SDK, SDK, 1.f, 0, 0, 0);

    // 5. V projection, transposed out: Vt[b][d][t] (M=1024, N=2048, K=1024),
    //    2-pass (A=WvT 2-limb, B=key hi), split output (B of 3-pass attn GEMM)
    mma_gemm<2,1,2><<<dim3(SLK/BN, SDK/BM, NB), 256, SM2>>>(
        wvh, wvl, kh, nullptr, bv, nullptr, Vth, Vtl,
        SLK, SDK, 1.f, 0, (long)SLK*SDK, (long)SDK*SLK);

    // 6. scores = (Qp @ Kp^T)/32 (M=2048, N=2048, K=1024 per batch), 2-pass
    mma_gemm<2,0,0><<<dim3(SLK/BN, SLQ/BM, NB), 256, SM2>>>(
        Qph, Qpl, Kph, nullptr, nullptr, S, nullptr, nullptr,
        SLK, SDK, 0.03125f, (long)SLQ*SDK, (long)SLK*SDK, (long)SLQ*SLK);

    // 7. softmax -> split fp16 weights
    softmax_kernel<<<NB*SLQ, 256>>>(S, Sh, Sl);

    // 8. out = weights @ Vt^T (M=2048, N=1024, K=2048 per batch), 3-pass (exact)
    mma_gemm<3,0,0><<<dim3(SDK/BN, SLQ/BM, NB), 256, SM3>>>(
        Sh, Sl, Vth, Vtl, nullptr, out, nullptr, nullptr,
        SDK, SLK, 1.f, (long)SLQ*SLK, (long)SDK*SLK, (long)SLQ*SDK);
}

// round 7
// speedup vs baseline: 4.4726x; 1.1351x over previous
#include <cuda_runtime.h>
#include <cuda_fp16.h>
#include <stdint.h>

#define NB  16
#define SLQ 2048
#define SLK 2048
#define SDQ 768
#define SDK 1024

// ---------------------------------------------------------------------------
// Device-global scratch (fp16 limb pairs: x ~= hi + lo, lo = fp16(x-hi))
// ---------------------------------------------------------------------------
__device__ __half g_qh [(size_t)NB*SLQ*SDQ];   // split(query)
__device__ __half g_ql [(size_t)NB*SLQ*SDQ];
__device__ __half g_kh [(size_t)NB*SLK*SDK];   // split(key)
__device__ __half g_kl [(size_t)NB*SLK*SDK];
__device__ __half g_wqh[SDK*SDQ];              // Wq^T hi  [1024,768]
__device__ __half g_wkh[SDK*SDK];              // Wk^T hi
__device__ __half g_wvh[SDK*SDK];              // Wv^T split (A of V proj)
__device__ __half g_wvl[SDK*SDK];
__device__ __half g_Qph[(size_t)NB*SLQ*SDK];   // projected Q split
__device__ __half g_Qpl[(size_t)NB*SLQ*SDK];
__device__ __half g_Kph[(size_t)NB*SLK*SDK];   // projected K hi only
__device__ __half g_Vth[(size_t)NB*SDK*SLK];   // projected V^T hi [B,Dk,Lk]
__device__ float  g_S [(size_t)NB*SLQ*SLK];    // scores fp32
__device__ __half g_Sh [(size_t)NB*SLQ*SLK];   // softmax weights split
__device__ __half g_Sl [(size_t)NB*SLQ*SLK];

// ---------------------------------------------------------------------------
// PTX helpers — baseline (non-'a') features only
// ---------------------------------------------------------------------------
__device__ __forceinline__ uint32_t smem_u32(const void* p) {
    uint32_t a;
    asm("{ .reg .u64 t; cvta.to.shared.u64 t, %1; cvt.u32.u64 %0, t; }"
        : "=r"(a) : "l"(p));
    return a;
}
__device__ __forceinline__ void cpa16(uint32_t dst, const void* src) {
    asm volatile("cp.async.cg.shared.global [%0], [%1], 16;"
                 :: "r"(dst), "l"(src) : "memory");
}
__device__ __forceinline__ void cpa_commit() {
    asm volatile("cp.async.commit_group;" ::: "memory");
}
template<int N>
__device__ __forceinline__ void cpa_wait() {
    asm volatile("cp.async.wait_group %0;" :: "n"(N) : "memory");
}
__device__ __forceinline__ void ldmx4(uint32_t* r, uint32_t addr) {
    asm volatile("ldmatrix.sync.aligned.m8n8.x4.shared.b16 {%0,%1,%2,%3}, [%4];"
                 : "=r"(r[0]), "=r"(r[1]), "=r"(r[2]), "=r"(r[3]) : "r"(addr));
}
__device__ __forceinline__ void mma16816(float* c, const uint32_t* a, const uint32_t* b) {
    asm volatile(
        "mma.sync.aligned.m16n8k16.row.col.f32.f16.f16.f32 "
        "{%0,%1,%2,%3}, {%4,%5,%6,%7}, {%8,%9}, {%0,%1,%2,%3};"
        : "+f"(c[0]), "+f"(c[1]), "+f"(c[2]), "+f"(c[3])
        : "r"(a[0]), "r"(a[1]), "r"(a[2]), "r"(a[3]), "r"(b[0]), "r"(b[1]));
}
__device__ __forceinline__ uint32_t sw128(uint32_t o) { return o ^ ((o >> 3) & 0x70); }

__device__ __forceinline__ uint32_t hsplit_pack(float x, float y, uint32_t& lopack) {
    __half hx = __float2half_rn(x), hy = __float2half_rn(y);
    __half lx = __float2half_rn(x - __half2float(hx));
    __half ly = __float2half_rn(y - __half2float(hy));
    lopack = (uint32_t)__half_as_ushort(lx) | ((uint32_t)__half_as_ushort(ly) << 16);
    return (uint32_t)__half_as_ushort(hx) | ((uint32_t)__half_as_ushort(hy) << 16);
}

// ---------------------------------------------------------------------------
// fp16 multi-pass HMMA GEMM:  D[M,N] = alpha * (A @ B^T) (+ bias)
//   A hi/lo [M,K] K-major; B hi (+lo if NPASS=3) [N,K] K-major.
//   CTA 128x256, BK=64 (128B rows, SW128), 2-stage cp.async, 8 warps (2m x 4n),
//   warp tile 64x64, mma.m16n8k16.
//   NPASS=2: AhBh + AlBh (B fp16-rounded).  NPASS=3: + AhBl.
// OUTMODE: 0 = fp32; 1 = split fp16 (Chi,Clo); 2 = fp16 hi only
// BIASMODE: 0 = none; 1 = per column; 2 = per row
// ---------------------------------------------------------------------------
#define BM 128
#define BN 256
#define BKC 64

template<int NPASS, int OUTMODE, int BIASMODE>
__global__ void __launch_bounds__(256, 1) mma_gemm(
    const __half* __restrict__ Ah, const __half* __restrict__ Al,
    const __half* __restrict__ Bh, const __half* __restrict__ Bl,
    const float* __restrict__ bias,
    float* __restrict__ Cf, __half* __restrict__ Chi, __half* __restrict__ Clo,
    int N, int K, float alpha,
    long batchA, long batchB, long batchC)
{
    constexpr uint32_t OFF_AL = 16384;
    constexpr uint32_t OFF_BH = 32768;
    constexpr uint32_t OFF_BL = 65536;
    constexpr uint32_t STAGE  = (NPASS == 3) ? 98304u : 65536u;

    extern __shared__ char smem[];
    const uint32_t sbase = smem_u32(smem);
    const int tid  = threadIdx.x;
    const int lane = tid & 31;
    const int wid  = tid >> 5;
    const int wm   = wid >> 2;   // 0..1  (m64)
    const int wn   = wid & 3;    // 0..3  (n64)
    const int row0 = blockIdx.y * BM;
    const int col0 = blockIdx.x * BN;
    const size_t zA = (size_t)blockIdx.z * batchA;
    const size_t zB = (size_t)blockIdx.z * batchB;
    const size_t zC = (size_t)blockIdx.z * batchC;

    const int r8 = tid >> 3;              // 0..31
    const uint32_t cb = (tid & 7) * 16;   // byte offset within 128B row

    auto load_stage = [&](int s, int k0) {
        const uint32_t st = sbase + s * STAGE;
        #pragma unroll
        for (int i = 0; i < 4; i++) {                 // A: 128 rows, 2 limbs
            int r = r8 + i * 32;
            size_t go = (size_t)(row0 + r) * K + k0;
            uint32_t so = sw128((uint32_t)(r * 128) + cb);
            cpa16(st + so,          (const char*)(Ah + zA + go) + cb);
            cpa16(st + OFF_AL + so, (const char*)(Al + zA + go) + cb);
        }
        #pragma unroll
        for (int i = 0; i < 8; i++) {                 // B: 256 rows
            int r = r8 + i * 32;
            size_t go = (size_t)(col0 + r) * K + k0;
            uint32_t so = sw128((uint32_t)(r * 128) + cb);
            cpa16(st + OFF_BH + so, (const char*)(Bh + zB + go) + cb);
            if (NPASS == 3)
                cpa16(st + OFF_BL + so, (const char*)(Bl + zB + go) + cb);
        }
        cpa_commit();
    };

    float c[4][8][4];
    #pragma unroll
    for (int i = 0; i < 4; i++)
        #pragma unroll
        for (int j = 0; j < 8; j++)
            #pragma unroll
            for (int k = 0; k < 4; k++) c[i][j][k] = 0.f;

    const int nk = K / BKC;
    load_stage(0, 0);
    load_stage(1, BKC);

    const int a_r = ((lane >> 3) & 1) * 8 + (lane & 7);
    const int a_k = ((lane >> 4) & 1) * 16;
    const int b_r = ((lane >> 4) & 1) * 8 + (lane & 7);
    const int b_k = ((lane >> 3) & 1) * 16;

    for (int i = 0; i < nk; i++) {
        if (i + 1 < nk) cpa_wait<1>(); else cpa_wait<0>();
        __syncthreads();

        const uint32_t st = sbase + (i & 1) * STAGE;
        #pragma unroll
        for (int ks = 0; ks < 4; ks++) {
            uint32_t ah[4][4], al[4][4];
            #pragma unroll
            for (int fm = 0; fm < 4; fm++) {
                int row = wm * 64 + fm * 16 + a_r;
                uint32_t so = sw128((uint32_t)(row * 128) + ks * 32 + a_k);
                ldmx4(ah[fm], st + so);
                ldmx4(al[fm], st + OFF_AL + so);
            }
            uint32_t bh_[4][4];
            #pragma unroll
            for (int g = 0; g < 4; g++) {
                int row = wn * 64 + g * 16 + b_r;
                uint32_t so = sw128((uint32_t)(row * 128) + ks * 32 + b_k);
                ldmx4(bh_[g], st + OFF_BH + so);
            }
            #pragma unroll
            for (int fm = 0; fm < 4; fm++)
                #pragma unroll
                for (int fn = 0; fn < 8; fn++)
                    mma16816(c[fm][fn], ah[fm], &bh_[fn >> 1][(fn & 1) * 2]);
            if (NPASS == 3) {
                uint32_t bl_[4][4];
                #pragma unroll
                for (int g = 0; g < 4; g++) {
                    int row = wn * 64 + g * 16 + b_r;
                    uint32_t so = sw128((uint32_t)(row * 128) + ks * 32 + b_k);
                    ldmx4(bl_[g], st + OFF_BL + so);
                }
                #pragma unroll
                for (int fm = 0; fm < 4; fm++)
                    #pragma unroll
                    for (int fn = 0; fn < 8; fn++)
                        mma16816(c[fm][fn], ah[fm], &bl_[fn >> 1][(fn & 1) * 2]);
            }
            #pragma unroll
            for (int fm = 0; fm < 4; fm++)
                #pragma unroll
                for (int fn = 0; fn < 8; fn++)
                    mma16816(c[fm][fn], al[fm], &bh_[fn >> 1][(fn & 1) * 2]);
        }
        if (i + 2 < nk) {
            __syncthreads();
            load_stage(i & 1, (i + 2) * BKC);
        }
    }

    // ---- epilogue -------------------------------------------------------
    #pragma unroll
    for (int fm = 0; fm < 4; fm++)
        #pragma unroll
        for (int fn = 0; fn < 8; fn++) {
            int row = row0 + wm * 64 + fm * 16 + (lane >> 2);
            int col = col0 + wn * 64 + fn * 8 + (lane & 3) * 2;
            float v0 = c[fm][fn][0] * alpha, v1 = c[fm][fn][1] * alpha;
            float v2 = c[fm][fn][2] * alpha, v3 = c[fm][fn][3] * alpha;
            if (BIASMODE == 1) {
                float b0 = bias[col], b1 = bias[col + 1];
                v0 += b0; v1 += b1; v2 += b0; v3 += b1;
            }
            if (BIASMODE == 2) {
                float rb0 = bias[row], rb1 = bias[row + 8];
                v0 += rb0; v1 += rb0; v2 += rb1; v3 += rb1;
            }
            size_t o0 = zC + (size_t)row * N + col;
            size_t o1 = o0 + (size_t)8 * N;
            if (OUTMODE == 0) {
                *(float2*)(Cf + o0) = make_float2(v0, v1);
                *(float2*)(Cf + o1) = make_float2(v2, v3);
            } else if (OUTMODE == 1) {
                uint32_t lo0, lo1;
                uint32_t hi0 = hsplit_pack(v0, v1, lo0);
                uint32_t hi1 = hsplit_pack(v2, v3, lo1);
                *(uint32_t*)(Chi + o0) = hi0;
                *(uint32_t*)(Clo + o0) = lo0;
                *(uint32_t*)(Chi + o1) = hi1;
                *(uint32_t*)(Clo + o1) = lo1;
            } else {
                uint32_t dmy0, dmy1;
                uint32_t hi0 = hsplit_pack(v0, v1, dmy0);
                uint32_t hi1 = hsplit_pack(v2, v3, dmy1);
                *(uint32_t*)(Chi + o0) = hi0;
                *(uint32_t*)(Chi + o1) = hi1;
            }
        }
}

// ---------------------------------------------------------------------------
// Elementwise split: fp32 -> (hi, lo) fp16.  n multiple of 4.
// ---------------------------------------------------------------------------
__global__ void split_kernel(const float* __restrict__ x,
                             __half* __restrict__ hi, __half* __restrict__ lo, size_t n)
{
    size_t i = ((size_t)blockIdx.x * blockDim.x + threadIdx.x) * 4;
    if (i >= n) return;
    float4 v = *(const float4*)(x + i);
    uint32_t l0, l1;
    uint32_t h0 = hsplit_pack(v.x, v.y, l0);
    uint32_t h1 = hsplit_pack(v.z, v.w, l1);
    *(uint2*)(hi + i) = make_uint2(h0, h1);
    *(uint2*)(lo + i) = make_uint2(l0, l1);
}

// ---------------------------------------------------------------------------
// Transposed split: W [K,N] fp32 -> Wt [N,K] fp16 (hi always, lo if WANTLO)
// ---------------------------------------------------------------------------
template<bool WANTLO>
__global__ void transpose_split_kernel(const float* __restrict__ W,
                                       __half* __restrict__ hi, __half* __restrict__ lo,
                                       int K, int N)
{
    __shared__ float t[32][33];
    int n0 = blockIdx.x * 32, k0 = blockIdx.y * 32;
    int x = threadIdx.x, y = threadIdx.y;
    #pragma unroll
    for (int j = 0; j < 32; j += 8)
        t[y + j][x] = W[(size_t)(k0 + y + j) * N + n0 + x];
    __syncthreads();
    #pragma unroll
    for (int j = 0; j < 32; j += 8) {
        float v = t[x][y + j];
        __half h = __float2half_rn(v);
        size_t o = (size_t)(n0 + y + j) * K + k0 + x;
        hi[o] = h;
        if (WANTLO) lo[o] = __float2half_rn(v - __half2float(h));
    }
}

// ---------------------------------------------------------------------------
// Row softmax over LK=2048; reads fp32, writes split fp16 weights.
// ---------------------------------------------------------------------------
__global__ void __launch_bounds__(256) softmax_kernel(
    const float* __restrict__ S, __half* __restrict__ Sh, __half* __restrict__ Sl)
{
    const float* p = S + (size_t)blockIdx.x * SLK;
    const int tid = threadIdx.x;

    float v[8];
    float mx = -1e30f;
    #pragma unroll
    for (int i = 0; i < 8; i++) { v[i] = p[tid + i * 256]; mx = fmaxf(mx, v[i]); }
    #pragma unroll
    for (int off = 16; off; off >>= 1)
        mx = fmaxf(mx, __shfl_xor_sync(0xffffffffu, mx, off));

    __shared__ float red[8];
    if ((tid & 31) == 0) red[tid >> 5] = mx;
    __syncthreads();
    float m2 = red[0];
    #pragma unroll
    for (int i = 1; i < 8; i++) m2 = fmaxf(m2, red[i]);
    __syncthreads();

    float s = 0.f;
    #pragma unroll
    for (int i = 0; i < 8; i++) { v[i] = __expf(v[i] - m2); s += v[i]; }
    #pragma unroll
    for (int off = 16; off; off >>= 1)
        s += __shfl_xor_sync(0xffffffffu, s, off);
    if ((tid & 31) == 0) red[tid >> 5] = s;
    __syncthreads();
    float tot = 0.f;
    #pragma unroll
    for (int i = 0; i < 8; i++) tot += red[i];

    float inv = 1.f / tot;
    size_t base = (size_t)blockIdx.x * SLK + tid;
    #pragma unroll
    for (int i = 0; i < 8; i++) {
        float w = v[i] * inv;
        __half h = __float2half_rn(w);
        Sh[base + i * 256] = h;
        Sl[base + i * 256] = __float2half_rn(w - __half2float(h));
    }
}

// ---------------------------------------------------------------------------
// kernel_launch
// ---------------------------------------------------------------------------
extern "C" void kernel_launch(void* const* d_in, const int* in_sizes, int n_in,
                              void* d_out, int out_size)
{
    const float* query = (const float*)d_in[0];
    const float* key   = (const float*)d_in[1];
    const float* Wq    = (const float*)d_in[2];
    const float* bq    = (const float*)d_in[3];
    const float* Wk    = (const float*)d_in[4];
    const float* bk    = (const float*)d_in[5];
    const float* Wv    = (const float*)d_in[6];
    const float* bv    = (const float*)d_in[7];
    float* out = (float*)d_out;

    __half *qh,*ql,*kh,*kl,*wqh,*wkh,*wvh,*wvl;
    __half *Qph,*Qpl,*Kph,*Vth,*Sh,*Sl;
    float *S;
    cudaGetSymbolAddress((void**)&qh,  g_qh);  cudaGetSymbolAddress((void**)&ql,  g_ql);
    cudaGetSymbolAddress((void**)&kh,  g_kh);  cudaGetSymbolAddress((void**)&kl,  g_kl);
    cudaGetSymbolAddress((void**)&wqh, g_wqh);
    cudaGetSymbolAddress((void**)&wkh, g_wkh);
    cudaGetSymbolAddress((void**)&wvh, g_wvh); cudaGetSymbolAddress((void**)&wvl, g_wvl);
    cudaGetSymbolAddress((void**)&Qph, g_Qph); cudaGetSymbolAddress((void**)&Qpl, g_Qpl);
    cudaGetSymbolAddress((void**)&Kph, g_Kph);
    cudaGetSymbolAddress((void**)&Vth, g_Vth);
    cudaGetSymbolAddress((void**)&S,   g_S);
    cudaGetSymbolAddress((void**)&Sh,  g_Sh);  cudaGetSymbolAddress((void**)&Sl,  g_Sl);

    const int SM2 = 131072;   // 2-pass: 2 stages x 64KB
    cudaFuncSetAttribute(mma_gemm<2,1,1>, cudaFuncAttributeMaxDynamicSharedMemorySize, SM2);
    cudaFuncSetAttribute(mma_gemm<2,2,1>, cudaFuncAttributeMaxDynamicSharedMemorySize, SM2);
    cudaFuncSetAttribute(mma_gemm<2,2,2>, cudaFuncAttributeMaxDynamicSharedMemorySize, SM2);
    cudaFuncSetAttribute(mma_gemm<2,0,0>, cudaFuncAttributeMaxDynamicSharedMemorySize, SM2);

    // 1. split inputs (2 fp16 limbs)
    {
        size_t nq = (size_t)NB * SLQ * SDQ;
        split_kernel<<<(unsigned)((nq/4 + 255)/256), 256>>>(query, qh, ql, nq);
        size_t nkk = (size_t)NB * SLK * SDK;
        split_kernel<<<(unsigned)((nkk/4 + 255)/256), 256>>>(key, kh, kl, nkk);
    }
    // 2. transpose weights: Wq/Wk hi-only (B of 2-pass GEMMs), Wv 2 limbs (A of V proj)
    transpose_split_kernel<false><<<dim3(SDK/32, SDQ/32), dim3(32,8)>>>(Wq, wqh, nullptr, SDQ, SDK);
    transpose_split_kernel<false><<<dim3(SDK/32, SDK/32), dim3(32,8)>>>(Wk, wkh, nullptr, SDK, SDK);
    transpose_split_kernel<true ><<<dim3(SDK/32, SDK/32), dim3(32,8)>>>(Wv, wvh, wvl, SDK, SDK);

    // 3. Q projection (M=32768, N=1024, K=768), 2-pass, split output
    mma_gemm<2,1,1><<<dim3(SDK/BN, (NB*SLQ)/BM, 1), 256, SM2>>>(
        qh, ql, wqh, nullptr, bq, nullptr, Qph, Qpl,
        SDK, SDQ, 1.f, 0, 0, 0);

    // 4. K projection (M=32768, N=1024, K=1024), 2-pass, hi-only output
    mma_gemm<2,2,1><<<dim3(SDK/BN, (NB*SLK)/BM, 1), 256, SM2>>>(
        kh, kl, wkh, nullptr, bk, nullptr, Kph, nullptr,
        SDK, SDK, 1.f, 0, 0, 0);

    // 5. V projection, transposed out: Vt[b][d][t] (M=1024, N=2048, K=1024),
    //    2-pass (A=WvT 2-limb, B=key hi), hi-only output (V fp16-rounded anyway)
    mma_gemm<2,2,2><<<dim3(SLK/BN, SDK/BM, NB), 256, SM2>>>(
        wvh, wvl, kh, nullptr, bv, nullptr, Vth, nullptr,
        SLK, SDK, 1.f, 0, (long)SLK*SDK, (long)SDK*SLK);

    // 6. scores = (Qp @ Kp^T)/32 (M=2048, N=2048, K=1024 per batch), 2-pass
    mma_gemm<2,0,0><<<dim3(SLK/BN, SLQ/BM, NB), 256, SM2>>>(
        Qph, Qpl, Kph, nullptr, nullptr, S, nullptr, nullptr,
        SLK, SDK, 0.03125f, (long)SLQ*SDK, (long)SLK*SDK, (long)SLQ*SLK);

    // 7. softmax -> split fp16 weights
    softmax_kernel<<<NB*SLQ, 256>>>(S, Sh, Sl);

    // 8. out = weights @ Vt^T (M=2048, N=1024, K=2048 per batch), 2-pass
    //    (Sh+Sl keep weight precision; V already fp16)
    mma_gemm<2,0,0><<<dim3(SDK/BN, SLQ/BM, NB), 256, SM2>>>(
        Sh, Sl, Vth, nullptr, nullptr, out, nullptr, nullptr,
        SDK, SLK, 1.f, (long)SLQ*SLK, (long)SDK*SLK, (long)SLQ*SDK);
}

// round 8
// speedup vs baseline: 7.7442x; 1.7315x over previous
#include <cuda_runtime.h>
#include <cuda_fp16.h>
#include <stdint.h>

#define NB  16
#define SLQ 2048
#define SLK 2048
#define SDQ 768
#define SDK 1024

// ---------------------------------------------------------------------------
// Device-global scratch — pure fp16 operands, fp32 only for scores
// ---------------------------------------------------------------------------
__device__ __half g_qh [(size_t)NB*SLQ*SDQ];   // fp16(query)
__device__ __half g_kh [(size_t)NB*SLK*SDK];   // fp16(key)
__device__ __half g_wqh[SDK*SDQ];              // fp16(Wq^T)  [1024,768]
__device__ __half g_wkh[SDK*SDK];              // fp16(Wk^T)
__device__ __half g_wvh[SDK*SDK];              // fp16(Wv^T)
__device__ __half g_Qph[(size_t)NB*SLQ*SDK];   // projected Q  [B,Lq,Dk]
__device__ __half g_Kph[(size_t)NB*SLK*SDK];   // projected K  [B,Lk,Dk]
__device__ __half g_Vth[(size_t)NB*SDK*SLK];   // projected V^T [B,Dk,Lk]
__device__ float  g_S [(size_t)NB*SLQ*SLK];    // scores fp32
__device__ __half g_Sh [(size_t)NB*SLQ*SLK];   // softmax weights fp16

// ---------------------------------------------------------------------------
// PTX helpers — baseline (non-'a') features only
// ---------------------------------------------------------------------------
__device__ __forceinline__ uint32_t smem_u32(const void* p) {
    uint32_t a;
    asm("{ .reg .u64 t; cvta.to.shared.u64 t, %1; cvt.u32.u64 %0, t; }"
        : "=r"(a) : "l"(p));
    return a;
}
__device__ __forceinline__ void cpa16(uint32_t dst, const void* src) {
    asm volatile("cp.async.cg.shared.global [%0], [%1], 16;"
                 :: "r"(dst), "l"(src) : "memory");
}
__device__ __forceinline__ void cpa_commit() {
    asm volatile("cp.async.commit_group;" ::: "memory");
}
template<int N>
__device__ __forceinline__ void cpa_wait() {
    asm volatile("cp.async.wait_group %0;" :: "n"(N) : "memory");
}
__device__ __forceinline__ void ldmx4(uint32_t* r, uint32_t addr) {
    asm volatile("ldmatrix.sync.aligned.m8n8.x4.shared.b16 {%0,%1,%2,%3}, [%4];"
                 : "=r"(r[0]), "=r"(r[1]), "=r"(r[2]), "=r"(r[3]) : "r"(addr));
}
__device__ __forceinline__ void mma16816(float* c, const uint32_t* a, const uint32_t* b) {
    asm volatile(
        "mma.sync.aligned.m16n8k16.row.col.f32.f16.f16.f32 "
        "{%0,%1,%2,%3}, {%4,%5,%6,%7}, {%8,%9}, {%0,%1,%2,%3};"
        : "+f"(c[0]), "+f"(c[1]), "+f"(c[2]), "+f"(c[3])
        : "r"(a[0]), "r"(a[1]), "r"(a[2]), "r"(a[3]), "r"(b[0]), "r"(b[1]));
}
__device__ __forceinline__ uint32_t sw128(uint32_t o) { return o ^ ((o >> 3) & 0x70); }

__device__ __forceinline__ uint32_t hpack(float x, float y) {
    __half hx = __float2half_rn(x), hy = __float2half_rn(y);
    return (uint32_t)__half_as_ushort(hx) | ((uint32_t)__half_as_ushort(hy) << 16);
}

// ---------------------------------------------------------------------------
// fp16 single-pass HMMA GEMM:  D[M,N] = alpha * (A @ B^T) (+ bias)
//   A [M,K] K-major fp16; B [N,K] K-major fp16.
//   CTA 128x256, BK=64 (128B rows, SW128), 2-stage cp.async, 8 warps (2m x 4n),
//   warp tile 64x64, mma.m16n8k16.
// OUTMODE: 0 = fp32; 2 = fp16
// BIASMODE: 0 = none; 1 = per column; 2 = per row
// ---------------------------------------------------------------------------
#define BM 128
#define BN 256
#define BKC 64
#define OFF_B  16384u
#define STAGE  49152u
#define GEMM_SMEM 98304      // 2 stages x 48KB

template<int OUTMODE, int BIASMODE>
__global__ void __launch_bounds__(256, 1) mma_gemm(
    const __half* __restrict__ Ah, const __half* __restrict__ Bh,
    const float* __restrict__ bias,
    float* __restrict__ Cf, __half* __restrict__ Chi,
    int N, int K, float alpha,
    long batchA, long batchB, long batchC)
{
    extern __shared__ char smem[];
    const uint32_t sbase = smem_u32(smem);
    const int tid  = threadIdx.x;
    const int lane = tid & 31;
    const int wid  = tid >> 5;
    const int wm   = wid >> 2;   // 0..1  (m64)
    const int wn   = wid & 3;    // 0..3  (n64)
    const int row0 = blockIdx.y * BM;
    const int col0 = blockIdx.x * BN;
    const size_t zA = (size_t)blockIdx.z * batchA;
    const size_t zB = (size_t)blockIdx.z * batchB;
    const size_t zC = (size_t)blockIdx.z * batchC;

    const int r8 = tid >> 3;              // 0..31
    const uint32_t cb = (tid & 7) * 16;   // byte offset within 128B row

    auto load_stage = [&](int s, int k0) {
        const uint32_t st = sbase + s * STAGE;
        #pragma unroll
        for (int i = 0; i < 4; i++) {                 // A: 128 rows
            int r = r8 + i * 32;
            size_t go = (size_t)(row0 + r) * K + k0;
            uint32_t so = sw128((uint32_t)(r * 128) + cb);
            cpa16(st + so, (const char*)(Ah + zA + go) + cb);
        }
        #pragma unroll
        for (int i = 0; i < 8; i++) {                 // B: 256 rows
            int r = r8 + i * 32;
            size_t go = (size_t)(col0 + r) * K + k0;
            uint32_t so = sw128((uint32_t)(r * 128) + cb);
            cpa16(st + OFF_B + so, (const char*)(Bh + zB + go) + cb);
        }
        cpa_commit();
    };

    float c[4][8][4];
    #pragma unroll
    for (int i = 0; i < 4; i++)
        #pragma unroll
        for (int j = 0; j < 8; j++)
            #pragma unroll
            for (int k = 0; k < 4; k++) c[i][j][k] = 0.f;

    const int nk = K / BKC;
    load_stage(0, 0);
    load_stage(1, BKC);

    const int a_r = ((lane >> 3) & 1) * 8 + (lane & 7);
    const int a_k = ((lane >> 4) & 1) * 16;
    const int b_r = ((lane >> 4) & 1) * 8 + (lane & 7);
    const int b_k = ((lane >> 3) & 1) * 16;

    for (int i = 0; i < nk; i++) {
        if (i + 1 < nk) cpa_wait<1>(); else cpa_wait<0>();
        __syncthreads();

        const uint32_t st = sbase + (i & 1) * STAGE;
        #pragma unroll
        for (int ks = 0; ks < 4; ks++) {
            uint32_t a_[4][4];
            #pragma unroll
            for (int fm = 0; fm < 4; fm++) {
                int row = wm * 64 + fm * 16 + a_r;
                uint32_t so = sw128((uint32_t)(row * 128) + ks * 32 + a_k);
                ldmx4(a_[fm], st + so);
            }
            uint32_t b_[4][4];
            #pragma unroll
            for (int g = 0; g < 4; g++) {
                int row = wn * 64 + g * 16 + b_r;
                uint32_t so = sw128((uint32_t)(row * 128) + ks * 32 + b_k);
                ldmx4(b_[g], st + OFF_B + so);
            }
            #pragma unroll
            for (int fm = 0; fm < 4; fm++)
                #pragma unroll
                for (int fn = 0; fn < 8; fn++)
                    mma16816(c[fm][fn], a_[fm], &b_[fn >> 1][(fn & 1) * 2]);
        }
        if (i + 2 < nk) {
            __syncthreads();
            load_stage(i & 1, (i + 2) * BKC);
        }
    }

    // ---- epilogue -------------------------------------------------------
    #pragma unroll
    for (int fm = 0; fm < 4; fm++)
        #pragma unroll
        for (int fn = 0; fn < 8; fn++) {
            int row = row0 + wm * 64 + fm * 16 + (lane >> 2);
            int col = col0 + wn * 64 + fn * 8 + (lane & 3) * 2;
            float v0 = c[fm][fn][0] * alpha, v1 = c[fm][fn][1] * alpha;
            float v2 = c[fm][fn][2] * alpha, v3 = c[fm][fn][3] * alpha;
            if (BIASMODE == 1) {
                float b0 = bias[col], b1 = bias[col + 1];
                v0 += b0; v1 += b1; v2 += b0; v3 += b1;
            }
            if (BIASMODE == 2) {
                float rb0 = bias[row], rb1 = bias[row + 8];
                v0 += rb0; v1 += rb0; v2 += rb1; v3 += rb1;
            }
            size_t o0 = zC + (size_t)row * N + col;
            size_t o1 = o0 + (size_t)8 * N;
            if (OUTMODE == 0) {
                *(float2*)(Cf + o0) = make_float2(v0, v1);
                *(float2*)(Cf + o1) = make_float2(v2, v3);
            } else {
                *(uint32_t*)(Chi + o0) = hpack(v0, v1);
                *(uint32_t*)(Chi + o1) = hpack(v2, v3);
            }
        }
}

// ---------------------------------------------------------------------------
// Elementwise convert: fp32 -> fp16.  n multiple of 8.
// ---------------------------------------------------------------------------
__global__ void cvt_kernel(const float* __restrict__ x,
                           __half* __restrict__ h, size_t n)
{
    size_t i = ((size_t)blockIdx.x * blockDim.x + threadIdx.x) * 8;
    if (i >= n) return;
    float4 v0 = *(const float4*)(x + i);
    float4 v1 = *(const float4*)(x + i + 4);
    uint4 o;
    o.x = hpack(v0.x, v0.y);
    o.y = hpack(v0.z, v0.w);
    o.z = hpack(v1.x, v1.y);
    o.w = hpack(v1.z, v1.w);
    *(uint4*)(h + i) = o;
}

// ---------------------------------------------------------------------------
// Transposed convert: W [K,N] fp32 -> Wt [N,K] fp16
// ---------------------------------------------------------------------------
__global__ void transpose_cvt_kernel(const float* __restrict__ W,
                                     __half* __restrict__ hi, int K, int N)
{
    __shared__ float t[32][33];
    int n0 = blockIdx.x * 32, k0 = blockIdx.y * 32;
    int x = threadIdx.x, y = threadIdx.y;
    #pragma unroll
    for (int j = 0; j < 32; j += 8)
        t[y + j][x] = W[(size_t)(k0 + y + j) * N + n0 + x];
    __syncthreads();
    #pragma unroll
    for (int j = 0; j < 32; j += 8)
        hi[(size_t)(n0 + y + j) * K + k0 + x] = __float2half_rn(t[x][y + j]);
}

// ---------------------------------------------------------------------------
// Row softmax over LK=2048; reads fp32, writes fp16 weights.
// ---------------------------------------------------------------------------
__global__ void __launch_bounds__(256) softmax_kernel(
    const float* __restrict__ S, __half* __restrict__ Sh)
{
    const float* p = S + (size_t)blockIdx.x * SLK;
    const int tid = threadIdx.x;

    float v[8];
    float mx = -1e30f;
    #pragma unroll
    for (int i = 0; i < 8; i++) { v[i] = p[tid + i * 256]; mx = fmaxf(mx, v[i]); }
    #pragma unroll
    for (int off = 16; off; off >>= 1)
        mx = fmaxf(mx, __shfl_xor_sync(0xffffffffu, mx, off));

    __shared__ float red[8];
    if ((tid & 31) == 0) red[tid >> 5] = mx;
    __syncthreads();
    float m2 = red[0];
    #pragma unroll
    for (int i = 1; i < 8; i++) m2 = fmaxf(m2, red[i]);
    __syncthreads();

    float s = 0.f;
    #pragma unroll
    for (int i = 0; i < 8; i++) { v[i] = __expf(v[i] - m2); s += v[i]; }
    #pragma unroll
    for (int off = 16; off; off >>= 1)
        s += __shfl_xor_sync(0xffffffffu, s, off);
    if ((tid & 31) == 0) red[tid >> 5] = s;
    __syncthreads();
    float tot = 0.f;
    #pragma unroll
    for (int i = 0; i < 8; i++) tot += red[i];

    float inv = 1.f / tot;
    size_t base = (size_t)blockIdx.x * SLK + tid;
    #pragma unroll
    for (int i = 0; i < 8; i++)
        Sh[base + i * 256] = __float2half_rn(v[i] * inv);
}

// ---------------------------------------------------------------------------
// kernel_launch
// ---------------------------------------------------------------------------
extern "C" void kernel_launch(void* const* d_in, const int* in_sizes, int n_in,
                              void* d_out, int out_size)
{
    const float* query = (const float*)d_in[0];
    const float* key   = (const float*)d_in[1];
    const float* Wq    = (const float*)d_in[2];
    const float* bq    = (const float*)d_in[3];
    const float* Wk    = (const float*)d_in[4];
    const float* bk    = (const float*)d_in[5];
    const float* Wv    = (const float*)d_in[6];
    const float* bv    = (const float*)d_in[7];
    float* out = (float*)d_out;

    __half *qh,*kh,*wqh,*wkh,*wvh,*Qph,*Kph,*Vth,*Sh;
    float *S;
    cudaGetSymbolAddress((void**)&qh,  g_qh);
    cudaGetSymbolAddress((void**)&kh,  g_kh);
    cudaGetSymbolAddress((void**)&wqh, g_wqh);
    cudaGetSymbolAddress((void**)&wkh, g_wkh);
    cudaGetSymbolAddress((void**)&wvh, g_wvh);
    cudaGetSymbolAddress((void**)&Qph, g_Qph);
    cudaGetSymbolAddress((void**)&Kph, g_Kph);
    cudaGetSymbolAddress((void**)&Vth, g_Vth);
    cudaGetSymbolAddress((void**)&S,   g_S);
    cudaGetSymbolAddress((void**)&Sh,  g_Sh);

    cudaFuncSetAttribute(mma_gemm<2,1>, cudaFuncAttributeMaxDynamicSharedMemorySize, GEMM_SMEM);
    cudaFuncSetAttribute(mma_gemm<2,2>, cudaFuncAttributeMaxDynamicSharedMemorySize, GEMM_SMEM);
    cudaFuncSetAttribute(mma_gemm<0,0>, cudaFuncAttributeMaxDynamicSharedMemorySize, GEMM_SMEM);

    // 1. convert inputs to fp16
    {
        size_t nq = (size_t)NB * SLQ * SDQ;
        cvt_kernel<<<(unsigned)((nq/8 + 255)/256), 256>>>(query, qh, nq);
        size_t nkk = (size_t)NB * SLK * SDK;
        cvt_kernel<<<(unsigned)((nkk/8 + 255)/256), 256>>>(key, kh, nkk);
    }
    // 2. transpose-convert weights (W[K,N] -> Wt[N,K] fp16)
    transpose_cvt_kernel<<<dim3(SDK/32, SDQ/32), dim3(32,8)>>>(Wq, wqh, SDQ, SDK);
    transpose_cvt_kernel<<<dim3(SDK/32, SDK/32), dim3(32,8)>>>(Wk, wkh, SDK, SDK);
    transpose_cvt_kernel<<<dim3(SDK/32, SDK/32), dim3(32,8)>>>(Wv, wvh, SDK, SDK);

    // 3. Q projection (M=32768, N=1024, K=768) -> fp16
    mma_gemm<2,1><<<dim3(SDK/BN, (NB*SLQ)/BM, 1), 256, GEMM_SMEM>>>(
        qh, wqh, bq, nullptr, Qph, SDK, SDQ, 1.f, 0, 0, 0);

    // 4. K projection (M=32768, N=1024, K=1024) -> fp16
    mma_gemm<2,1><<<dim3(SDK/BN, (NB*SLK)/BM, 1), 256, GEMM_SMEM>>>(
        kh, wkh, bk, nullptr, Kph, SDK, SDK, 1.f, 0, 0, 0);

    // 5. V projection, transposed out: Vt[b][d][t] (M=1024, N=2048, K=1024)
    mma_gemm<2,2><<<dim3(SLK/BN, SDK/BM, NB), 256, GEMM_SMEM>>>(
        wvh, kh, bv, nullptr, Vth,
        SLK, SDK, 1.f, 0, (long)SLK*SDK, (long)SDK*SLK);

    // 6. scores = (Qp @ Kp^T)/32 (M=2048, N=2048, K=1024 per batch) -> fp32
    mma_gemm<0,0><<<dim3(SLK/BN, SLQ/BM, NB), 256, GEMM_SMEM>>>(
        Qph, Kph, nullptr, S, nullptr,
        SLK, SDK, 0.03125f, (long)SLQ*SDK, (long)SLK*SDK, (long)SLQ*SLK);

    // 7. softmax -> fp16 weights
    softmax_kernel<<<NB*SLQ, 256>>>(S, Sh);

    // 8. out = weights @ Vt^T (M=2048, N=1024, K=2048 per batch) -> fp32
    mma_gemm<0,0><<<dim3(SDK/BN, SLQ/BM, NB), 256, GEMM_SMEM>>>(
        Sh, Vth, nullptr, out, nullptr,
        SDK, SLK, 1.f, (long)SLQ*SLK, (long)SDK*SLK, (long)SLQ*SDK);
}

// round 9
// speedup vs baseline: 8.9557x; 1.1564x over previous
#include <cuda_runtime.h>
#include <cuda_fp16.h>
#include <stdint.h>

#define NB  16
#define SLQ 2048
#define SLK 2048
#define SDQ 768
#define SDK 1024

// ---------------------------------------------------------------------------
// Device-global scratch
// ---------------------------------------------------------------------------
__device__ __half g_qh  [(size_t)NB*SLQ*SDQ];   // fp16(query)
__device__ __half g_kh  [(size_t)NB*SLK*SDK];   // fp16(key)
__device__ __half g_wq16[SDQ*SDK];              // fp16(Wq)   [768,1024]
__device__ __half g_wk16[SDK*SDK];              // fp16(Wk)   [1024,1024]
__device__ __half g_wvt [SDK*SDK];              // fp16(Wv^T) [1024,1024]
__device__ __half g_M2  [SDQ*SDK];              // Wq@Wk^T    [768,1024]
__device__ __half g_Kred[(size_t)NB*SLK*SDQ];   // key@M2^T   [B*Lk,768]
__device__ __half g_Vth [(size_t)NB*SDK*SLK];   // V^T        [B,Dk,Lk]
__device__ __half g_Sf  [(size_t)NB*SLQ*SLK];   // scores fp16 (incl. bias)
__device__ __half g_Sh  [(size_t)NB*SLQ*SLK];   // softmax weights fp16
__device__ float  g_w   [SDK];                  // Wk @ bq
__device__ float  g_cs  [NB*SLK];               // (key @ w)/32 per-col bias

// ---------------------------------------------------------------------------
// PTX helpers — baseline (non-'a') features only
// ---------------------------------------------------------------------------
__device__ __forceinline__ uint32_t smem_u32(const void* p) {
    uint32_t a;
    asm("{ .reg .u64 t; cvta.to.shared.u64 t, %1; cvt.u32.u64 %0, t; }"
        : "=r"(a) : "l"(p));
    return a;
}
__device__ __forceinline__ void cpa16(uint32_t dst, const void* src) {
    asm volatile("cp.async.cg.shared.global [%0], [%1], 16;"
                 :: "r"(dst), "l"(src) : "memory");
}
__device__ __forceinline__ void cpa_commit() {
    asm volatile("cp.async.commit_group;" ::: "memory");
}
template<int N>
__device__ __forceinline__ void cpa_wait() {
    asm volatile("cp.async.wait_group %0;" :: "n"(N) : "memory");
}
__device__ __forceinline__ void ldmx4(uint32_t* r, uint32_t addr) {
    asm volatile("ldmatrix.sync.aligned.m8n8.x4.shared.b16 {%0,%1,%2,%3}, [%4];"
                 : "=r"(r[0]), "=r"(r[1]), "=r"(r[2]), "=r"(r[3]) : "r"(addr));
}
__device__ __forceinline__ void mma16816(float* c, const uint32_t* a, const uint32_t* b) {
    asm volatile(
        "mma.sync.aligned.m16n8k16.row.col.f32.f16.f16.f32 "
        "{%0,%1,%2,%3}, {%4,%5,%6,%7}, {%8,%9}, {%0,%1,%2,%3};"
        : "+f"(c[0]), "+f"(c[1]), "+f"(c[2]), "+f"(c[3])
        : "r"(a[0]), "r"(a[1]), "r"(a[2]), "r"(a[3]), "r"(b[0]), "r"(b[1]));
}
__device__ __forceinline__ uint32_t sw128(uint32_t o) { return o ^ ((o >> 3) & 0x70); }

__device__ __forceinline__ uint32_t hpack(float x, float y) {
    __half hx = __float2half_rn(x), hy = __float2half_rn(y);
    return (uint32_t)__half_as_ushort(hx) | ((uint32_t)__half_as_ushort(hy) << 16);
}

// ---------------------------------------------------------------------------
// fp16 single-pass HMMA GEMM:  D[M,N] = alpha * (A @ B^T) (+ bias)
//   A [M,K] K-major fp16; B [N,K] K-major fp16. K mult of 64, N mult of 256,
//   M mult of 128. CTA 128x256, 3-stage cp.async (one sync/iter), 8 warps,
//   warp tile 64x64, mma.m16n8k16.
// OUTMODE: 0 = fp32; 2 = fp16
// BIASMODE: 0 = none; 1 = per column (fp32, + batch stride); 2 = per row
// ---------------------------------------------------------------------------
#define BM 128
#define BN 256
#define BKC 64
#define OFF_B  16384u
#define STAGE  49152u
#define GEMM_SMEM 147456      // 3 stages x 48KB

template<int OUTMODE, int BIASMODE>
__global__ void __launch_bounds__(256, 1) mma_gemm(
    const __half* __restrict__ Ah, const __half* __restrict__ Bh,
    const float* __restrict__ bias,
    float* __restrict__ Cf, __half* __restrict__ Chi,
    int N, int K, float alpha,
    long batchA, long batchB, long batchC, long biasBatch)
{
    extern __shared__ char smem[];
    const uint32_t sbase = smem_u32(smem);
    const int tid  = threadIdx.x;
    const int lane = tid & 31;
    const int wid  = tid >> 5;
    const int wm   = wid >> 2;   // 0..1  (m64)
    const int wn   = wid & 3;    // 0..3  (n64)
    const int row0 = blockIdx.y * BM;
    const int col0 = blockIdx.x * BN;
    const size_t zA = (size_t)blockIdx.z * batchA;
    const size_t zB = (size_t)blockIdx.z * batchB;
    const size_t zC = (size_t)blockIdx.z * batchC;
    const float* bp = bias ? bias + (size_t)blockIdx.z * biasBatch : bias;

    const int r8 = tid >> 3;              // 0..31
    const uint32_t cb = (tid & 7) * 16;   // byte offset within 128B row

    auto load_stage = [&](int s, int k0) {
        const uint32_t st = sbase + s * STAGE;
        #pragma unroll
        for (int i = 0; i < 4; i++) {                 // A: 128 rows
            int r = r8 + i * 32;
            size_t go = (size_t)(row0 + r) * K + k0;
            uint32_t so = sw128((uint32_t)(r * 128) + cb);
            cpa16(st + so, (const char*)(Ah + zA + go) + cb);
        }
        #pragma unroll
        for (int i = 0; i < 8; i++) {                 // B: 256 rows
            int r = r8 + i * 32;
            size_t go = (size_t)(col0 + r) * K + k0;
            uint32_t so = sw128((uint32_t)(r * 128) + cb);
            cpa16(st + OFF_B + so, (const char*)(Bh + zB + go) + cb);
        }
        cpa_commit();
    };

    float c[4][8][4];
    #pragma unroll
    for (int i = 0; i < 4; i++)
        #pragma unroll
        for (int j = 0; j < 8; j++)
            #pragma unroll
            for (int k = 0; k < 4; k++) c[i][j][k] = 0.f;

    const int nk = K / BKC;
    load_stage(0, 0);
    load_stage(1, BKC);

    const int a_r = ((lane >> 3) & 1) * 8 + (lane & 7);
    const int a_k = ((lane >> 4) & 1) * 16;
    const int b_r = ((lane >> 4) & 1) * 8 + (lane & 7);
    const int b_k = ((lane >> 3) & 1) * 16;

    for (int i = 0; i < nk; i++) {
        if (i + 1 < nk) cpa_wait<1>(); else cpa_wait<0>();
        __syncthreads();                      // stage i%3 ready; (i-1)%3 freed
        if (i + 2 < nk) load_stage((i + 2) % 3, (i + 2) * BKC);

        const uint32_t st = sbase + (i % 3) * STAGE;
        #pragma unroll
        for (int ks = 0; ks < 4; ks++) {
            uint32_t a_[4][4];
            #pragma unroll
            for (int fm = 0; fm < 4; fm++) {
                int row = wm * 64 + fm * 16 + a_r;
                uint32_t so = sw128((uint32_t)(row * 128) + ks * 32 + a_k);
                ldmx4(a_[fm], st + so);
            }
            uint32_t b_[4][4];
            #pragma unroll
            for (int g = 0; g < 4; g++) {
                int row = wn * 64 + g * 16 + b_r;
                uint32_t so = sw128((uint32_t)(row * 128) + ks * 32 + b_k);
                ldmx4(b_[g], st + OFF_B + so);
            }
            #pragma unroll
            for (int fm = 0; fm < 4; fm++)
                #pragma unroll
                for (int fn = 0; fn < 8; fn++)
                    mma16816(c[fm][fn], a_[fm], &b_[fn >> 1][(fn & 1) * 2]);
        }
    }

    // ---- epilogue -------------------------------------------------------
    #pragma unroll
    for (int fm = 0; fm < 4; fm++)
        #pragma unroll
        for (int fn = 0; fn < 8; fn++) {
            int row = row0 + wm * 64 + fm * 16 + (lane >> 2);
            int col = col0 + wn * 64 + fn * 8 + (lane & 3) * 2;
            float v0 = c[fm][fn][0] * alpha, v1 = c[fm][fn][1] * alpha;
            float v2 = c[fm][fn][2] * alpha, v3 = c[fm][fn][3] * alpha;
            if (BIASMODE == 1) {
                float b0 = bp[col], b1 = bp[col + 1];
                v0 += b0; v1 += b1; v2 += b0; v3 += b1;
            }
            if (BIASMODE == 2) {
                float rb0 = bp[row], rb1 = bp[row + 8];
                v0 += rb0; v1 += rb0; v2 += rb1; v3 += rb1;
            }
            size_t o0 = zC + (size_t)row * N + col;
            size_t o1 = o0 + (size_t)8 * N;
            if (OUTMODE == 0) {
                *(float2*)(Cf + o0) = make_float2(v0, v1);
                *(float2*)(Cf + o1) = make_float2(v2, v3);
            } else {
                *(uint32_t*)(Chi + o0) = hpack(v0, v1);
                *(uint32_t*)(Chi + o1) = hpack(v2, v3);
            }
        }
}

// ---------------------------------------------------------------------------
// Elementwise convert: fp32 -> fp16.  n multiple of 8.
// ---------------------------------------------------------------------------
__global__ void cvt_kernel(const float* __restrict__ x,
                           __half* __restrict__ h, size_t n)
{
    size_t i = ((size_t)blockIdx.x * blockDim.x + threadIdx.x) * 8;
    if (i >= n) return;
    float4 v0 = *(const float4*)(x + i);
    float4 v1 = *(const float4*)(x + i + 4);
    uint4 o;
    o.x = hpack(v0.x, v0.y);
    o.y = hpack(v0.z, v0.w);
    o.z = hpack(v1.x, v1.y);
    o.w = hpack(v1.z, v1.w);
    *(uint4*)(h + i) = o;
}

// ---------------------------------------------------------------------------
// Transposed convert: W [K,N] fp32 -> Wt [N,K] fp16   (Wv only)
// ---------------------------------------------------------------------------
__global__ void transpose_cvt_kernel(const float* __restrict__ W,
                                     __half* __restrict__ hi, int K, int N)
{
    __shared__ float t[32][33];
    int n0 = blockIdx.x * 32, k0 = blockIdx.y * 32;
    int x = threadIdx.x, y = threadIdx.y;
    #pragma unroll
    for (int j = 0; j < 32; j += 8)
        t[y + j][x] = W[(size_t)(k0 + y + j) * N + n0 + x];
    __syncthreads();
    #pragma unroll
    for (int j = 0; j < 32; j += 8)
        hi[(size_t)(n0 + y + j) * K + k0 + x] = __float2half_rn(t[x][y + j]);
}

// ---------------------------------------------------------------------------
// w = Wk @ bq  (w[i] = dot(Wk[i,:], bq)).  One block per row, coalesced.
// ---------------------------------------------------------------------------
__global__ void __launch_bounds__(256) wvec_kernel(
    const float* __restrict__ Wk, const float* __restrict__ bq,
    float* __restrict__ w)
{
    const int i = blockIdx.x;
    const int tid = threadIdx.x;
    float s = 0.f;
    #pragma unroll
    for (int j = 0; j < 4; j++) {
        int o = tid + j * 256;
        s += Wk[(size_t)i * SDK + o] * bq[o];
    }
    #pragma unroll
    for (int off = 16; off; off >>= 1)
        s += __shfl_xor_sync(0xffffffffu, s, off);
    __shared__ float red[8];
    if ((tid & 31) == 0) red[tid >> 5] = s;
    __syncthreads();
    if (tid == 0) {
        float t = 0.f;
        #pragma unroll
        for (int k = 0; k < 8; k++) t += red[k];
        w[i] = t;
    }
}

// ---------------------------------------------------------------------------
// cs[j] = dot(key[j,:], w) / 32.  One block per key row.
// ---------------------------------------------------------------------------
__global__ void __launch_bounds__(256) cvec_kernel(
    const float* __restrict__ key, const float* __restrict__ w,
    float* __restrict__ cs)
{
    const size_t j = blockIdx.x;
    const int tid = threadIdx.x;
    const float* kr = key + j * SDK;
    float s = 0.f;
    #pragma unroll
    for (int t = 0; t < 4; t++) {
        int o = tid + t * 256;
        s += kr[o] * w[o];
    }
    #pragma unroll
    for (int off = 16; off; off >>= 1)
        s += __shfl_xor_sync(0xffffffffu, s, off);
    __shared__ float red[8];
    if ((tid & 31) == 0) red[tid >> 5] = s;
    __syncthreads();
    if (tid == 0) {
        float t = 0.f;
        #pragma unroll
        for (int k = 0; k < 8; k++) t += red[k];
        cs[j] = t * 0.03125f;
    }
}

// ---------------------------------------------------------------------------
// Row softmax over LK=2048; reads fp16 scores, writes fp16 weights.
// ---------------------------------------------------------------------------
__global__ void __launch_bounds__(256) softmax_kernel(
    const __half* __restrict__ S, __half* __restrict__ Sh)
{
    const __half* p = S + (size_t)blockIdx.x * SLK;
    const int tid = threadIdx.x;

    float v[8];
    float mx = -1e30f;
    #pragma unroll
    for (int i = 0; i < 8; i++) {
        v[i] = __half2float(p[tid + i * 256]);
        mx = fmaxf(mx, v[i]);
    }
    #pragma unroll
    for (int off = 16; off; off >>= 1)
        mx = fmaxf(mx, __shfl_xor_sync(0xffffffffu, mx, off));

    __shared__ float red[8];
    if ((tid & 31) == 0) red[tid >> 5] = mx;
    __syncthreads();
    float m2 = red[0];
    #pragma unroll
    for (int i = 1; i < 8; i++) m2 = fmaxf(m2, red[i]);
    __syncthreads();

    float s = 0.f;
    #pragma unroll
    for (int i = 0; i < 8; i++) { v[i] = __expf(v[i] - m2); s += v[i]; }
    #pragma unroll
    for (int off = 16; off; off >>= 1)
        s += __shfl_xor_sync(0xffffffffu, s, off);
    if ((tid & 31) == 0) red[tid >> 5] = s;
    __syncthreads();
    float tot = 0.f;
    #pragma unroll
    for (int i = 0; i < 8; i++) tot += red[i];

    float inv = 1.f / tot;
    size_t base = (size_t)blockIdx.x * SLK + tid;
    #pragma unroll
    for (int i = 0; i < 8; i++)
        Sh[base + i * 256] = __float2half_rn(v[i] * inv);
}

// ---------------------------------------------------------------------------
// kernel_launch
// ---------------------------------------------------------------------------
extern "C" void kernel_launch(void* const* d_in, const int* in_sizes, int n_in,
                              void* d_out, int out_size)
{
    const float* query = (const float*)d_in[0];
    const float* key   = (const float*)d_in[1];
    const float* Wq    = (const float*)d_in[2];
    const float* bq    = (const float*)d_in[3];
    const float* Wk    = (const float*)d_in[4];
    const float* bk    = (const float*)d_in[5];   // vanishes under softmax
    const float* Wv    = (const float*)d_in[6];
    const float* bv    = (const float*)d_in[7];
    float* out = (float*)d_out;
    (void)bk;

    __half *qh,*kh,*wq16,*wk16,*wvt,*M2,*Kred,*Vth,*Sf,*Sh;
    float *w,*cs;
    cudaGetSymbolAddress((void**)&qh,   g_qh);
    cudaGetSymbolAddress((void**)&kh,   g_kh);
    cudaGetSymbolAddress((void**)&wq16, g_wq16);
    cudaGetSymbolAddress((void**)&wk16, g_wk16);
    cudaGetSymbolAddress((void**)&wvt,  g_wvt);
    cudaGetSymbolAddress((void**)&M2,   g_M2);
    cudaGetSymbolAddress((void**)&Kred, g_Kred);
    cudaGetSymbolAddress((void**)&Vth,  g_Vth);
    cudaGetSymbolAddress((void**)&Sf,   g_Sf);
    cudaGetSymbolAddress((void**)&Sh,   g_Sh);
    cudaGetSymbolAddress((void**)&w,    g_w);
    cudaGetSymbolAddress((void**)&cs,   g_cs);

    cudaFuncSetAttribute(mma_gemm<2,0>, cudaFuncAttributeMaxDynamicSharedMemorySize, GEMM_SMEM);
    cudaFuncSetAttribute(mma_gemm<2,1>, cudaFuncAttributeMaxDynamicSharedMemorySize, GEMM_SMEM);
    cudaFuncSetAttribute(mma_gemm<2,2>, cudaFuncAttributeMaxDynamicSharedMemorySize, GEMM_SMEM);
    cudaFuncSetAttribute(mma_gemm<0,0>, cudaFuncAttributeMaxDynamicSharedMemorySize, GEMM_SMEM);

    // 1. converts
    {
        size_t nq = (size_t)NB * SLQ * SDQ;
        cvt_kernel<<<(unsigned)((nq/8 + 255)/256), 256>>>(query, qh, nq);
        size_t nkk = (size_t)NB * SLK * SDK;
        cvt_kernel<<<(unsigned)((nkk/8 + 255)/256), 256>>>(key, kh, nkk);
        cvt_kernel<<<(SDQ*SDK/8 + 255)/256, 256>>>(Wq, wq16, (size_t)SDQ*SDK);
        cvt_kernel<<<(SDK*SDK/8 + 255)/256, 256>>>(Wk, wk16, (size_t)SDK*SDK);
    }
    transpose_cvt_kernel<<<dim3(SDK/32, SDK/32), dim3(32,8)>>>(Wv, wvt, SDK, SDK);

    // 2. exact bias column: w = Wk@bq ; cs = (key@w)/32
    wvec_kernel<<<SDK, 256>>>(Wk, bq, w);
    cvec_kernel<<<NB*SLK, 256>>>(key, w, cs);

    // 3. M2 = Wq @ Wk^T  (M=768, N=1024, K=1024) -> fp16
    mma_gemm<2,0><<<dim3(SDK/BN, SDQ/BM, 1), 256, GEMM_SMEM>>>(
        wq16, wk16, nullptr, nullptr, M2, SDK, SDK, 1.f, 0, 0, 0, 0);

    // 4. Kred = key @ M2^T  (M=32768, N=768, K=1024) -> fp16
    mma_gemm<2,0><<<dim3(SDQ/BN, (NB*SLK)/BM, 1), 256, GEMM_SMEM>>>(
        kh, M2, nullptr, nullptr, Kred, SDQ, SDK, 1.f, 0, 0, 0, 0);

    // 5. V projection, transposed out: Vt[b][d][t] (M=1024, N=2048, K=1024)
    mma_gemm<2,2><<<dim3(SLK/BN, SDK/BM, NB), 256, GEMM_SMEM>>>(
        wvt, kh, bv, nullptr, Vth,
        SLK, SDK, 1.f, 0, (long)SLK*SDK, (long)SDK*SLK, 0);

    // 6. scores = query @ Kred^T / 32 + cs[col]  (M=2048, N=2048, K=768/batch)
    mma_gemm<2,1><<<dim3(SLK/BN, SLQ/BM, NB), 256, GEMM_SMEM>>>(
        qh, Kred, cs, nullptr, Sf,
        SLK, SDQ, 0.03125f, (long)SLQ*SDQ, (long)SLK*SDQ, (long)SLQ*SLK, SLK);

    // 7. softmax -> fp16 weights
    softmax_kernel<<<NB*SLQ, 256>>>(Sf, Sh);

    // 8. out = weights @ Vt^T (M=2048, N=1024, K=2048 per batch) -> fp32
    mma_gemm<0,0><<<dim3(SDK/BN, SLQ/BM, NB), 256, GEMM_SMEM>>>(
        Sh, Vth, nullptr, out, nullptr,
        SDK, SLK, 1.f, (long)SLQ*SLK, (long)SDK*SLK, (long)SLQ*SDK, 0);
}

// round 10
// speedup vs baseline: 9.0748x; 1.0133x over previous
#include <cuda_runtime.h>
#include <cuda_fp16.h>
#include <stdint.h>

#define NB  16
#define SLQ 2048
#define SLK 2048
#define SDQ 768
#define SDK 1024
#define LOG2E 1.4426950408889634f

// ---------------------------------------------------------------------------
// Device-global scratch
// ---------------------------------------------------------------------------
__device__ __half g_qh  [(size_t)NB*SLQ*SDQ];   // fp16(query)
__device__ __half g_kh  [(size_t)NB*SLK*SDK];   // fp16(key)
__device__ __half g_wq16[SDQ*SDK];              // fp16(Wq)   [768,1024]
__device__ __half g_wk16[SDK*SDK];              // fp16(Wk)   [1024,1024]
__device__ __half g_wvt [SDK*SDK];              // fp16(Wv^T) [1024,1024]
__device__ __half g_M2  [SDQ*SDK];              // Wq@Wk^T    [768,1024]
__device__ __half g_Kred[(size_t)NB*SLK*SDQ];   // key@M2^T   [B*Lk,768]
__device__ __half g_Vth [(size_t)NB*SDK*SLK];   // V^T        [B,Dk,Lk]
__device__ __half g_Sf  [(size_t)NB*SLQ*SLK];   // exp(scores) fp16
__device__ float  g_part[(size_t)NB*SLQ*8];     // per-CTA partial row sums
__device__ float  g_rs  [NB*SLQ];               // 1 / row sum
__device__ float  g_w   [SDK];                  // Wk @ bq
__device__ float  g_cs  [NB*SLK];               // (key@w)/32 * log2e

// ---------------------------------------------------------------------------
// PTX helpers — baseline (non-'a') features only
// ---------------------------------------------------------------------------
__device__ __forceinline__ uint32_t smem_u32(const void* p) {
    uint32_t a;
    asm("{ .reg .u64 t; cvta.to.shared.u64 t, %1; cvt.u32.u64 %0, t; }"
        : "=r"(a) : "l"(p));
    return a;
}
__device__ __forceinline__ void cpa16(uint32_t dst, const void* src) {
    asm volatile("cp.async.cg.shared.global [%0], [%1], 16;"
                 :: "r"(dst), "l"(src) : "memory");
}
__device__ __forceinline__ void cpa_commit() {
    asm volatile("cp.async.commit_group;" ::: "memory");
}
template<int N>
__device__ __forceinline__ void cpa_wait() {
    asm volatile("cp.async.wait_group %0;" :: "n"(N) : "memory");
}
__device__ __forceinline__ void ldmx4(uint32_t* r, uint32_t addr) {
    asm volatile("ldmatrix.sync.aligned.m8n8.x4.shared.b16 {%0,%1,%2,%3}, [%4];"
                 : "=r"(r[0]), "=r"(r[1]), "=r"(r[2]), "=r"(r[3]) : "r"(addr));
}
__device__ __forceinline__ void mma16816(float* c, const uint32_t* a, const uint32_t* b) {
    asm volatile(
        "mma.sync.aligned.m16n8k16.row.col.f32.f16.f16.f32 "
        "{%0,%1,%2,%3}, {%4,%5,%6,%7}, {%8,%9}, {%0,%1,%2,%3};"
        : "+f"(c[0]), "+f"(c[1]), "+f"(c[2]), "+f"(c[3])
        : "r"(a[0]), "r"(a[1]), "r"(a[2]), "r"(a[3]), "r"(b[0]), "r"(b[1]));
}
__device__ __forceinline__ uint32_t sw128(uint32_t o) { return o ^ ((o >> 3) & 0x70); }

__device__ __forceinline__ uint32_t hpack(float x, float y) {
    __half hx = __float2half_rn(x), hy = __float2half_rn(y);
    return (uint32_t)__half_as_ushort(hx) | ((uint32_t)__half_as_ushort(hy) << 16);
}

// ---------------------------------------------------------------------------
// fp16 single-pass HMMA GEMM:  D[M,N] = alpha * (A @ B^T) (+ bias / scale)
//   A [M,K] K-major fp16; B [N,K] K-major fp16.
//   CTA 128x256, BK=64 (SW128), 3-stage cp.async (one sync/iter), 8 warps,
//   warp tile 64x64, mma.m16n8k16.
// OUTMODE: 0 = fp32; 2 = fp16;
//          3 = fp16 exp2(v) + deterministic per-CTA row-sum partials in Cf
// BIASMODE: 0 = none; 1 = per column (fp32, batched); 2 = per row;
//           3 = multiply by per-row scale (fp32, batched)
// ---------------------------------------------------------------------------
#define BM 128
#define BN 256
#define BKC 64
#define OFF_B  16384u
#define STAGE  49152u
#define GEMM_SMEM 147456      // 3 stages x 48KB

template<int OUTMODE, int BIASMODE>
__global__ void __launch_bounds__(256, 1) mma_gemm(
    const __half* __restrict__ Ah, const __half* __restrict__ Bh,
    const float* __restrict__ bias,
    float* __restrict__ Cf, __half* __restrict__ Chi,
    int N, int K, float alpha,
    long batchA, long batchB, long batchC, long biasBatch)
{
    extern __shared__ char smem[];
    const uint32_t sbase = smem_u32(smem);
    const int tid  = threadIdx.x;
    const int lane = tid & 31;
    const int wid  = tid >> 5;
    const int wm   = wid >> 2;   // 0..1  (m64)
    const int wn   = wid & 3;    // 0..3  (n64)
    const int row0 = blockIdx.y * BM;
    const int col0 = blockIdx.x * BN;
    const size_t zA = (size_t)blockIdx.z * batchA;
    const size_t zB = (size_t)blockIdx.z * batchB;
    const size_t zC = (size_t)blockIdx.z * batchC;
    const float* bp = bias ? bias + (size_t)blockIdx.z * biasBatch : bias;

    const int r8 = tid >> 3;              // 0..31
    const uint32_t cb = (tid & 7) * 16;   // byte offset within 128B row

    auto load_stage = [&](int s, int k0) {
        const uint32_t st = sbase + s * STAGE;
        #pragma unroll
        for (int i = 0; i < 4; i++) {                 // A: 128 rows
            int r = r8 + i * 32;
            size_t go = (size_t)(row0 + r) * K + k0;
            uint32_t so = sw128((uint32_t)(r * 128) + cb);
            cpa16(st + so, (const char*)(Ah + zA + go) + cb);
        }
        #pragma unroll
        for (int i = 0; i < 8; i++) {                 // B: 256 rows
            int r = r8 + i * 32;
            size_t go = (size_t)(col0 + r) * K + k0;
            uint32_t so = sw128((uint32_t)(r * 128) + cb);
            cpa16(st + OFF_B + so, (const char*)(Bh + zB + go) + cb);
        }
        cpa_commit();
    };

    float c[4][8][4];
    #pragma unroll
    for (int i = 0; i < 4; i++)
        #pragma unroll
        for (int j = 0; j < 8; j++)
            #pragma unroll
            for (int k = 0; k < 4; k++) c[i][j][k] = 0.f;

    const int nk = K / BKC;
    load_stage(0, 0);
    load_stage(1, BKC);

    const int a_r = ((lane >> 3) & 1) * 8 + (lane & 7);
    const int a_k = ((lane >> 4) & 1) * 16;
    const int b_r = ((lane >> 4) & 1) * 8 + (lane & 7);
    const int b_k = ((lane >> 3) & 1) * 16;

    for (int i = 0; i < nk; i++) {
        if (i + 1 < nk) cpa_wait<1>(); else cpa_wait<0>();
        __syncthreads();                      // stage i%3 ready; (i-1)%3 freed
        if (i + 2 < nk) load_stage((i + 2) % 3, (i + 2) * BKC);

        const uint32_t st = sbase + (i % 3) * STAGE;
        #pragma unroll
        for (int ks = 0; ks < 4; ks++) {
            uint32_t a_[4][4];
            #pragma unroll
            for (int fm = 0; fm < 4; fm++) {
                int row = wm * 64 + fm * 16 + a_r;
                uint32_t so = sw128((uint32_t)(row * 128) + ks * 32 + a_k);
                ldmx4(a_[fm], st + so);
            }
            uint32_t b_[4][4];
            #pragma unroll
            for (int g = 0; g < 4; g++) {
                int row = wn * 64 + g * 16 + b_r;
                uint32_t so = sw128((uint32_t)(row * 128) + ks * 32 + b_k);
                ldmx4(b_[g], st + OFF_B + so);
            }
            #pragma unroll
            for (int fm = 0; fm < 4; fm++)
                #pragma unroll
                for (int fn = 0; fn < 8; fn++)
                    mma16816(c[fm][fn], a_[fm], &b_[fn >> 1][(fn & 1) * 2]);
        }
    }

    // ---- epilogue -------------------------------------------------------
    float rsum[8];
    if (OUTMODE == 3) {
        #pragma unroll
        for (int r = 0; r < 8; r++) rsum[r] = 0.f;
    }

    #pragma unroll
    for (int fm = 0; fm < 4; fm++)
        #pragma unroll
        for (int fn = 0; fn < 8; fn++) {
            int row = row0 + wm * 64 + fm * 16 + (lane >> 2);
            int col = col0 + wn * 64 + fn * 8 + (lane & 3) * 2;
            float v0 = c[fm][fn][0] * alpha, v1 = c[fm][fn][1] * alpha;
            float v2 = c[fm][fn][2] * alpha, v3 = c[fm][fn][3] * alpha;
            if (BIASMODE == 1) {
                float b0 = bp[col], b1 = bp[col + 1];
                v0 += b0; v1 += b1; v2 += b0; v3 += b1;
            }
            if (BIASMODE == 2) {
                float rb0 = bp[row], rb1 = bp[row + 8];
                v0 += rb0; v1 += rb0; v2 += rb1; v3 += rb1;
            }
            if (BIASMODE == 3) {
                float rb0 = bp[row], rb1 = bp[row + 8];
                v0 *= rb0; v1 *= rb0; v2 *= rb1; v3 *= rb1;
            }
            size_t o0 = zC + (size_t)row * N + col;
            size_t o1 = o0 + (size_t)8 * N;
            if (OUTMODE == 0) {
                *(float2*)(Cf + o0) = make_float2(v0, v1);
                *(float2*)(Cf + o1) = make_float2(v2, v3);
            } else if (OUTMODE == 2) {
                *(uint32_t*)(Chi + o0) = hpack(v0, v1);
                *(uint32_t*)(Chi + o1) = hpack(v2, v3);
            } else {                                  // OUTMODE == 3
                float e0 = exp2f(v0), e1 = exp2f(v1);
                float e2 = exp2f(v2), e3 = exp2f(v3);
                *(uint32_t*)(Chi + o0) = hpack(e0, e1);
                *(uint32_t*)(Chi + o1) = hpack(e2, e3);
                rsum[fm * 2]     += e0 + e1;
                rsum[fm * 2 + 1] += e2 + e3;
            }
        }

    if (OUTMODE == 3) {
        // deterministic row-sum reduction -> per-CTA partials
        #pragma unroll
        for (int r = 0; r < 8; r++) {
            rsum[r] += __shfl_xor_sync(0xffffffffu, rsum[r], 1);
            rsum[r] += __shfl_xor_sync(0xffffffffu, rsum[r], 2);
        }
        __syncthreads();                      // safe to reuse stage smem
        float* arr = (float*)smem;            // [4][128]
        if ((lane & 3) == 0) {
            #pragma unroll
            for (int fm = 0; fm < 4; fm++) {
                int r0 = wm * 64 + fm * 16 + (lane >> 2);
                arr[wn * 128 + r0]     = rsum[fm * 2];
                arr[wn * 128 + r0 + 8] = rsum[fm * 2 + 1];
            }
        }
        __syncthreads();
        if (tid < 128) {
            float s = (arr[tid] + arr[128 + tid]) + (arr[256 + tid] + arr[384 + tid]);
            size_t grow = (size_t)blockIdx.z * (gridDim.y * BM) + row0 + tid;
            Cf[grow * gridDim.x + blockIdx.x] = s;
        }
    }
}

// ---------------------------------------------------------------------------
// Elementwise convert: fp32 -> fp16.  n multiple of 8.
// ---------------------------------------------------------------------------
__global__ void cvt_kernel(const float* __restrict__ x,
                           __half* __restrict__ h, size_t n)
{
    size_t i = ((size_t)blockIdx.x * blockDim.x + threadIdx.x) * 8;
    if (i >= n) return;
    float4 v0 = *(const float4*)(x + i);
    float4 v1 = *(const float4*)(x + i + 4);
    uint4 o;
    o.x = hpack(v0.x, v0.y);
    o.y = hpack(v0.z, v0.w);
    o.z = hpack(v1.x, v1.y);
    o.w = hpack(v1.z, v1.w);
    *(uint4*)(h + i) = o;
}

// ---------------------------------------------------------------------------
// Transposed convert: W [K,N] fp32 -> Wt [N,K] fp16   (Wv only)
// ---------------------------------------------------------------------------
__global__ void transpose_cvt_kernel(const float* __restrict__ W,
                                     __half* __restrict__ hi, int K, int N)
{
    __shared__ float t[32][33];
    int n0 = blockIdx.x * 32, k0 = blockIdx.y * 32;
    int x = threadIdx.x, y = threadIdx.y;
    #pragma unroll
    for (int j = 0; j < 32; j += 8)
        t[y + j][x] = W[(size_t)(k0 + y + j) * N + n0 + x];
    __syncthreads();
    #pragma unroll
    for (int j = 0; j < 32; j += 8)
        hi[(size_t)(n0 + y + j) * K + k0 + x] = __float2half_rn(t[x][y + j]);
}

// ---------------------------------------------------------------------------
// w = Wk @ bq  (fp32 exact).  One block per row.
// ---------------------------------------------------------------------------
__global__ void __launch_bounds__(256) wvec_kernel(
    const float* __restrict__ Wk, const float* __restrict__ bq,
    float* __restrict__ w)
{
    const int i = blockIdx.x;
    const int tid = threadIdx.x;
    float s = 0.f;
    #pragma unroll
    for (int j = 0; j < 4; j++) {
        int o = tid + j * 256;
        s += Wk[(size_t)i * SDK + o] * bq[o];
    }
    #pragma unroll
    for (int off = 16; off; off >>= 1)
        s += __shfl_xor_sync(0xffffffffu, s, off);
    __shared__ float red[8];
    if ((tid & 31) == 0) red[tid >> 5] = s;
    __syncthreads();
    if (tid == 0) {
        float t = 0.f;
        #pragma unroll
        for (int k = 0; k < 8; k++) t += red[k];
        w[i] = t;
    }
}

// ---------------------------------------------------------------------------
// cs[j] = dot(kh[j,:], w) * (log2e/32).  One block per key row, fp16 key.
// ---------------------------------------------------------------------------
__global__ void __launch_bounds__(256) cvec_kernel(
    const __half* __restrict__ kh, const float* __restrict__ w,
    float* __restrict__ cs)
{
    const size_t j = blockIdx.x;
    const int tid = threadIdx.x;
    const __half* kr = kh + j * SDK;
    float s = 0.f;
    #pragma unroll
    for (int t = 0; t < 4; t++) {
        int o = tid + t * 256;
        s += __half2float(kr[o]) * w[o];
    }
    #pragma unroll
    for (int off = 16; off; off >>= 1)
        s += __shfl_xor_sync(0xffffffffu, s, off);
    __shared__ float red[8];
    if ((tid & 31) == 0) red[tid >> 5] = s;
    __syncthreads();
    if (tid == 0) {
        float t = 0.f;
        #pragma unroll
        for (int k = 0; k < 8; k++) t += red[k];
        cs[j] = t * (0.03125f * LOG2E);
    }
}

// ---------------------------------------------------------------------------
// rs[i] = 1 / sum(part[i][0..8))   (deterministic, fixed order)
// ---------------------------------------------------------------------------
__global__ void __launch_bounds__(256) rowinv_kernel(
    const float* __restrict__ part, float* __restrict__ rs)
{
    int i = blockIdx.x * 256 + threadIdx.x;
    const float* p = part + (size_t)i * 8;
    float s = ((p[0] + p[1]) + (p[2] + p[3])) + ((p[4] + p[5]) + (p[6] + p[7]));
    rs[i] = 1.f / s;
}

// ---------------------------------------------------------------------------
// kernel_launch
// ---------------------------------------------------------------------------
extern "C" void kernel_launch(void* const* d_in, const int* in_sizes, int n_in,
                              void* d_out, int out_size)
{
    const float* query = (const float*)d_in[0];
    const float* key   = (const float*)d_in[1];
    const float* Wq    = (const float*)d_in[2];
    const float* bq    = (const float*)d_in[3];
    const float* Wk    = (const float*)d_in[4];
    const float* bk    = (const float*)d_in[5];   // vanishes under softmax
    const float* Wv    = (const float*)d_in[6];
    const float* bv    = (const float*)d_in[7];
    float* out = (float*)d_out;
    (void)bk;

    __half *qh,*kh,*wq16,*wk16,*wvt,*M2,*Kred,*Vth,*Sf;
    float *w,*cs,*part,*rs;
    cudaGetSymbolAddress((void**)&qh,   g_qh);
    cudaGetSymbolAddress((void**)&kh,   g_kh);
    cudaGetSymbolAddress((void**)&wq16, g_wq16);
    cudaGetSymbolAddress((void**)&wk16, g_wk16);
    cudaGetSymbolAddress((void**)&wvt,  g_wvt);
    cudaGetSymbolAddress((void**)&M2,   g_M2);
    cudaGetSymbolAddress((void**)&Kred, g_Kred);
    cudaGetSymbolAddress((void**)&Vth,  g_Vth);
    cudaGetSymbolAddress((void**)&Sf,   g_Sf);
    cudaGetSymbolAddress((void**)&w,    g_w);
    cudaGetSymbolAddress((void**)&cs,   g_cs);
    cudaGetSymbolAddress((void**)&part, g_part);
    cudaGetSymbolAddress((void**)&rs,   g_rs);

    cudaFuncSetAttribute(mma_gemm<2,0>, cudaFuncAttributeMaxDynamicSharedMemorySize, GEMM_SMEM);
    cudaFuncSetAttribute(mma_gemm<2,2>, cudaFuncAttributeMaxDynamicSharedMemorySize, GEMM_SMEM);
    cudaFuncSetAttribute(mma_gemm<3,1>, cudaFuncAttributeMaxDynamicSharedMemorySize, GEMM_SMEM);
    cudaFuncSetAttribute(mma_gemm<0,3>, cudaFuncAttributeMaxDynamicSharedMemorySize, GEMM_SMEM);

    // 1. converts
    {
        size_t nq = (size_t)NB * SLQ * SDQ;
        cvt_kernel<<<(unsigned)((nq/8 + 255)/256), 256>>>(query, qh, nq);
        size_t nkk = (size_t)NB * SLK * SDK;
        cvt_kernel<<<(unsigned)((nkk/8 + 255)/256), 256>>>(key, kh, nkk);
        cvt_kernel<<<(SDQ*SDK/8 + 255)/256, 256>>>(Wq, wq16, (size_t)SDQ*SDK);
        cvt_kernel<<<(SDK*SDK/8 + 255)/256, 256>>>(Wk, wk16, (size_t)SDK*SDK);
    }
    transpose_cvt_kernel<<<dim3(SDK/32, SDK/32), dim3(32,8)>>>(Wv, wvt, SDK, SDK);

    // 2. bias column (log2-domain): w = Wk@bq ; cs = (kh@w) * log2e/32
    wvec_kernel<<<SDK, 256>>>(Wk, bq, w);
    cvec_kernel<<<NB*SLK, 256>>>(kh, w, cs);

    // 3. M2 = Wq @ Wk^T  (M=768, N=1024, K=1024) -> fp16
    mma_gemm<2,0><<<dim3(SDK/BN, SDQ/BM, 1), 256, GEMM_SMEM>>>(
        wq16, wk16, nullptr, nullptr, M2, SDK, SDK, 1.f, 0, 0, 0, 0);

    // 4. Kred = key @ M2^T  (M=32768, N=768, K=1024) -> fp16
    mma_gemm<2,0><<<dim3(SDQ/BN, (NB*SLK)/BM, 1), 256, GEMM_SMEM>>>(
        kh, M2, nullptr, nullptr, Kred, SDQ, SDK, 1.f, 0, 0, 0, 0);

    // 5. V projection, transposed out: Vt[b][d][t] (M=1024, N=2048, K=1024)
    mma_gemm<2,2><<<dim3(SLK/BN, SDK/BM, NB), 256, GEMM_SMEM>>>(
        wvt, kh, bv, nullptr, Vth,
        SLK, SDK, 1.f, 0, (long)SLK*SDK, (long)SDK*SLK, 0);

    // 6. Sf = exp(query @ Kred^T / 32 + cs)  (log2-domain: alpha=log2e/32),
    //    plus deterministic per-CTA row-sum partials
    mma_gemm<3,1><<<dim3(SLK/BN, SLQ/BM, NB), 256, GEMM_SMEM>>>(
        qh, Kred, cs, part, Sf,
        SLK, SDQ, 0.03125f * LOG2E,
        (long)SLQ*SDQ, (long)SLK*SDQ, (long)SLQ*SLK, SLK);

    // 7. row-sum reciprocals
    rowinv_kernel<<<NB*SLQ/256, 256>>>(part, rs);

    // 8. out = (Sf @ Vt^T) * rs[row]  (M=2048, N=1024, K=2048 per batch)
    mma_gemm<0,3><<<dim3(SDK/BN, SLQ/BM, NB), 256, GEMM_SMEM>>>(
        Sf, Vth, rs, out, nullptr,
        SDK, SLK, 1.f, (long)SLQ*SLK, (long)SDK*SLK, (long)SLQ*SDK, SLQ);
}

// round 11
// speedup vs baseline: 9.4173x; 1.0377x over previous
#include <cuda_runtime.h>
#include <cuda_fp16.h>
#include <stdint.h>

#define NB  16
#define SLQ 2048
#define SLK 2048
#define SDQ 768
#define SDK 1024
#define LOG2E 1.4426950408889634f

// ---------------------------------------------------------------------------
// Device-global scratch
// ---------------------------------------------------------------------------
__device__ __half g_qh  [(size_t)NB*SLQ*SDQ];   // fp16(query)
__device__ __half g_kh  [(size_t)NB*SLK*SDK];   // fp16(key)
__device__ __half g_wq16[SDQ*SDK];              // fp16(Wq)   [768,1024]
__device__ __half g_wk16[SDK*SDK];              // fp16(Wk)   [1024,1024]
__device__ __half g_wvt [SDK*SDK];              // fp16(Wv^T) [1024,1024]
__device__ __half g_M2  [SDQ*SDK];              // Wq@Wk^T    [768,1024]
__device__ __half g_Kred[(size_t)NB*SLK*SDQ];   // key@M2^T   [B*Lk,768]
__device__ __half g_Vth [(size_t)NB*SDK*SLK];   // V^T        [B,Dk,Lk]
__device__ __half g_Sf  [(size_t)NB*SLQ*SLK];   // exp(scores) fp16
__device__ float  g_part[(size_t)NB*SLQ*8];     // per-CTA partial row sums
__device__ float  g_rs  [NB*SLQ];               // 1 / row sum
__device__ float  g_w   [SDK];                  // Wk @ bq
__device__ float  g_cs  [NB*SLK];               // (key@w)/32 * log2e

// ---------------------------------------------------------------------------
// PTX helpers — baseline (non-'a') features only
// ---------------------------------------------------------------------------
__device__ __forceinline__ uint32_t smem_u32(const void* p) {
    uint32_t a;
    asm("{ .reg .u64 t; cvta.to.shared.u64 t, %1; cvt.u32.u64 %0, t; }"
        : "=r"(a) : "l"(p));
    return a;
}
__device__ __forceinline__ void cpa16(uint32_t dst, const void* src) {
    asm volatile("cp.async.cg.shared.global [%0], [%1], 16;"
                 :: "r"(dst), "l"(src) : "memory");
}
__device__ __forceinline__ void cpa_commit() {
    asm volatile("cp.async.commit_group;" ::: "memory");
}
template<int N>
__device__ __forceinline__ void cpa_wait() {
    asm volatile("cp.async.wait_group %0;" :: "n"(N) : "memory");
}
__device__ __forceinline__ void ldmx4(uint32_t* r, uint32_t addr) {
    asm volatile("ldmatrix.sync.aligned.m8n8.x4.shared.b16 {%0,%1,%2,%3}, [%4];"
                 : "=r"(r[0]), "=r"(r[1]), "=r"(r[2]), "=r"(r[3]) : "r"(addr));
}
__device__ __forceinline__ void mma16816(float* c, const uint32_t* a, const uint32_t* b) {
    asm volatile(
        "mma.sync.aligned.m16n8k16.row.col.f32.f16.f16.f32 "
        "{%0,%1,%2,%3}, {%4,%5,%6,%7}, {%8,%9}, {%0,%1,%2,%3};"
        : "+f"(c[0]), "+f"(c[1]), "+f"(c[2]), "+f"(c[3])
        : "r"(a[0]), "r"(a[1]), "r"(a[2]), "r"(a[3]), "r"(b[0]), "r"(b[1]));
}
__device__ __forceinline__ uint32_t sw128(uint32_t o) { return o ^ ((o >> 3) & 0x70); }

__device__ __forceinline__ uint32_t hpack(float x, float y) {
    __half hx = __float2half_rn(x), hy = __float2half_rn(y);
    return (uint32_t)__half_as_ushort(hx) | ((uint32_t)__half_as_ushort(hy) << 16);
}

// ---------------------------------------------------------------------------
// fp16 single-pass HMMA GEMM:  D[M,N] = alpha * (A @ B^T) (+ bias / scale)
//   A [M,K] K-major fp16; B [N,K] K-major fp16.
//   CTA 128x256, BK=64 (SW128), 4-stage cp.async (one sync/iter), 8 warps,
//   warp tile 64x64, mma.m16n8k16.
// OUTMODE: 0 = fp32; 2 = fp16;
//          3 = fp16 exp2(v) + deterministic per-CTA row-sum partials in Cf
// BIASMODE: 0 = none; 1 = per column (fp32, batched); 2 = per row;
//           3 = multiply by per-row scale (fp32, batched)
// ---------------------------------------------------------------------------
#define BM 128
#define BN 256
#define BKC 64
#define OFF_B  16384u
#define STAGE  49152u
#define NSTG   4
#define GEMM_SMEM (NSTG * 49152)     // 196608

template<int OUTMODE, int BIASMODE>
__global__ void __launch_bounds__(256, 1) mma_gemm(
    const __half* __restrict__ Ah, const __half* __restrict__ Bh,
    const float* __restrict__ bias,
    float* __restrict__ Cf, __half* __restrict__ Chi,
    int N, int K, float alpha,
    long batchA, long batchB, long batchC, long biasBatch)
{
    extern __shared__ char smem[];
    const uint32_t sbase = smem_u32(smem);
    const int tid  = threadIdx.x;
    const int lane = tid & 31;
    const int wid  = tid >> 5;
    const int wm   = wid >> 2;   // 0..1  (m64)
    const int wn   = wid & 3;    // 0..3  (n64)
    const int row0 = blockIdx.y * BM;
    const int col0 = blockIdx.x * BN;
    const size_t zA = (size_t)blockIdx.z * batchA;
    const size_t zB = (size_t)blockIdx.z * batchB;
    const size_t zC = (size_t)blockIdx.z * batchC;
    const float* bp = bias ? bias + (size_t)blockIdx.z * biasBatch : bias;

    const int r8 = tid >> 3;              // 0..31
    const uint32_t cb = (tid & 7) * 16;   // byte offset within 128B row

    // Hoisted loader invariants: swizzled smem offsets + global row bases.
    uint32_t soA[4], soB[8];
    const char *pA[4], *pB[8];
    #pragma unroll
    for (int i = 0; i < 4; i++) {
        int r = r8 + i * 32;
        soA[i] = sw128((uint32_t)(r * 128) + cb);
        pA[i]  = (const char*)(Ah + zA + (size_t)(row0 + r) * K) + cb;
    }
    #pragma unroll
    for (int i = 0; i < 8; i++) {
        int r = r8 + i * 32;
        soB[i] = sw128((uint32_t)(r * 128) + cb);
        pB[i]  = (const char*)(Bh + zB + (size_t)(col0 + r) * K) + cb;
    }

    auto load_stage = [&](int s, int k0) {
        const uint32_t st = sbase + s * STAGE;
        const size_t kb = (size_t)k0 * 2;          // bytes along K
        #pragma unroll
        for (int i = 0; i < 4; i++)
            cpa16(st + soA[i], pA[i] + kb);
        #pragma unroll
        for (int i = 0; i < 8; i++)
            cpa16(st + OFF_B + soB[i], pB[i] + kb);
        cpa_commit();
    };

    float c[4][8][4];
    #pragma unroll
    for (int i = 0; i < 4; i++)
        #pragma unroll
        for (int j = 0; j < 8; j++)
            #pragma unroll
            for (int k = 0; k < 4; k++) c[i][j][k] = 0.f;

    const int nk = K / BKC;                // >= 12 for all our shapes
    load_stage(0, 0);
    load_stage(1, BKC);
    load_stage(2, 2 * BKC);

    const int a_r = ((lane >> 3) & 1) * 8 + (lane & 7);
    const int a_k = ((lane >> 4) & 1) * 16;
    const int b_r = ((lane >> 4) & 1) * 8 + (lane & 7);
    const int b_k = ((lane >> 3) & 1) * 16;

    for (int i = 0; i < nk; i++) {
        // ensure cp.async group i has completed
        if (i + 3 <= nk)      cpa_wait<2>();
        else if (i + 2 == nk) cpa_wait<1>();
        else                  cpa_wait<0>();
        __syncthreads();                  // stage i%4 ready; (i-1)%4 freed
        if (i + 3 < nk) load_stage((i + 3) % NSTG, (i + 3) * BKC);

        const uint32_t st = sbase + (i % NSTG) * STAGE;
        #pragma unroll
        for (int ks = 0; ks < 4; ks++) {
            uint32_t a_[4][4];
            #pragma unroll
            for (int fm = 0; fm < 4; fm++) {
                int row = wm * 64 + fm * 16 + a_r;
                uint32_t so = sw128((uint32_t)(row * 128) + ks * 32 + a_k);
                ldmx4(a_[fm], st + so);
            }
            uint32_t b_[4][4];
            #pragma unroll
            for (int g = 0; g < 4; g++) {
                int row = wn * 64 + g * 16 + b_r;
                uint32_t so = sw128((uint32_t)(row * 128) + ks * 32 + b_k);
                ldmx4(b_[g], st + OFF_B + so);
            }
            #pragma unroll
            for (int fm = 0; fm < 4; fm++)
                #pragma unroll
                for (int fn = 0; fn < 8; fn++)
                    mma16816(c[fm][fn], a_[fm], &b_[fn >> 1][(fn & 1) * 2]);
        }
    }

    // ---- epilogue -------------------------------------------------------
    float rsum[8];
    if (OUTMODE == 3) {
        #pragma unroll
        for (int r = 0; r < 8; r++) rsum[r] = 0.f;
    }

    #pragma unroll
    for (int fm = 0; fm < 4; fm++)
        #pragma unroll
        for (int fn = 0; fn < 8; fn++) {
            int row = row0 + wm * 64 + fm * 16 + (lane >> 2);
            int col = col0 + wn * 64 + fn * 8 + (lane & 3) * 2;
            float v0 = c[fm][fn][0] * alpha, v1 = c[fm][fn][1] * alpha;
            float v2 = c[fm][fn][2] * alpha, v3 = c[fm][fn][3] * alpha;
            if (BIASMODE == 1) {
                float b0 = bp[col], b1 = bp[col + 1];
                v0 += b0; v1 += b1; v2 += b0; v3 += b1;
            }
            if (BIASMODE == 2) {
                float rb0 = bp[row], rb1 = bp[row + 8];
                v0 += rb0; v1 += rb0; v2 += rb1; v3 += rb1;
            }
            if (BIASMODE == 3) {
                float rb0 = bp[row], rb1 = bp[row + 8];
                v0 *= rb0; v1 *= rb0; v2 *= rb1; v3 *= rb1;
            }
            size_t o0 = zC + (size_t)row * N + col;
            size_t o1 = o0 + (size_t)8 * N;
            if (OUTMODE == 0) {
                *(float2*)(Cf + o0) = make_float2(v0, v1);
                *(float2*)(Cf + o1) = make_float2(v2, v3);
            } else if (OUTMODE == 2) {
                *(uint32_t*)(Chi + o0) = hpack(v0, v1);
                *(uint32_t*)(Chi + o1) = hpack(v2, v3);
            } else {                                  // OUTMODE == 3
                float e0 = exp2f(v0), e1 = exp2f(v1);
                float e2 = exp2f(v2), e3 = exp2f(v3);
                *(uint32_t*)(Chi + o0) = hpack(e0, e1);
                *(uint32_t*)(Chi + o1) = hpack(e2, e3);
                rsum[fm * 2]     += e0 + e1;
                rsum[fm * 2 + 1] += e2 + e3;
            }
        }

    if (OUTMODE == 3) {
        // deterministic row-sum reduction -> per-CTA partials
        #pragma unroll
        for (int r = 0; r < 8; r++) {
            rsum[r] += __shfl_xor_sync(0xffffffffu, rsum[r], 1);
            rsum[r] += __shfl_xor_sync(0xffffffffu, rsum[r], 2);
        }
        __syncthreads();                      // safe to reuse stage smem
        float* arr = (float*)smem;            // [4][128]
        if ((lane & 3) == 0) {
            #pragma unroll
            for (int fm = 0; fm < 4; fm++) {
                int r0 = wm * 64 + fm * 16 + (lane >> 2);
                arr[wn * 128 + r0]     = rsum[fm * 2];
                arr[wn * 128 + r0 + 8] = rsum[fm * 2 + 1];
            }
        }
        __syncthreads();
        if (tid < 128) {
            float s = (arr[tid] + arr[128 + tid]) + (arr[256 + tid] + arr[384 + tid]);
            size_t grow = (size_t)blockIdx.z * (gridDim.y * BM) + row0 + tid;
            Cf[grow * gridDim.x + blockIdx.x] = s;
        }
    }
}

// ---------------------------------------------------------------------------
// Merged convert: 4 segments of fp32 -> fp16.  All sizes multiples of 2048.
// ---------------------------------------------------------------------------
__global__ void __launch_bounds__(256) cvt4_kernel(
    const float* __restrict__ s0, __half* __restrict__ d0, unsigned B0,
    const float* __restrict__ s1, __half* __restrict__ d1, unsigned B1,
    const float* __restrict__ s2, __half* __restrict__ d2, unsigned B2,
    const float* __restrict__ s3, __half* __restrict__ d3)
{
    unsigned b = blockIdx.x;
    const float* s; __half* d;
    if (b < B0)                { s = s0; d = d0; }
    else if (b < B0 + B1)      { s = s1; d = d1; b -= B0; }
    else if (b < B0 + B1 + B2) { s = s2; d = d2; b -= B0 + B1; }
    else                       { s = s3; d = d3; b -= B0 + B1 + B2; }
    size_t i = ((size_t)b * 256 + threadIdx.x) * 8;
    float4 v0 = *(const float4*)(s + i);
    float4 v1 = *(const float4*)(s + i + 4);
    uint4 o;
    o.x = hpack(v0.x, v0.y);
    o.y = hpack(v0.z, v0.w);
    o.z = hpack(v1.x, v1.y);
    o.w = hpack(v1.z, v1.w);
    *(uint4*)(d + i) = o;
}

// ---------------------------------------------------------------------------
// Transposed convert: W [K,N] fp32 -> Wt [N,K] fp16   (Wv only)
// ---------------------------------------------------------------------------
__global__ void transpose_cvt_kernel(const float* __restrict__ W,
                                     __half* __restrict__ hi, int K, int N)
{
    __shared__ float t[32][33];
    int n0 = blockIdx.x * 32, k0 = blockIdx.y * 32;
    int x = threadIdx.x, y = threadIdx.y;
    #pragma unroll
    for (int j = 0; j < 32; j += 8)
        t[y + j][x] = W[(size_t)(k0 + y + j) * N + n0 + x];
    __syncthreads();
    #pragma unroll
    for (int j = 0; j < 32; j += 8)
        hi[(size_t)(n0 + y + j) * K + k0 + x] = __float2half_rn(t[x][y + j]);
}

// ---------------------------------------------------------------------------
// w = Wk @ bq  (fp32 exact).  One block per row.
// ---------------------------------------------------------------------------
__global__ void __launch_bounds__(256) wvec_kernel(
    const float* __restrict__ Wk, const float* __restrict__ bq,
    float* __restrict__ w)
{
    const int i = blockIdx.x;
    const int tid = threadIdx.x;
    float s = 0.f;
    #pragma unroll
    for (int j = 0; j < 4; j++) {
        int o = tid + j * 256;
        s += Wk[(size_t)i * SDK + o] * bq[o];
    }
    #pragma unroll
    for (int off = 16; off; off >>= 1)
        s += __shfl_xor_sync(0xffffffffu, s, off);
    __shared__ float red[8];
    if ((tid & 31) == 0) red[tid >> 5] = s;
    __syncthreads();
    if (tid == 0) {
        float t = 0.f;
        #pragma unroll
        for (int k = 0; k < 8; k++) t += red[k];
        w[i] = t;
    }
}

// ---------------------------------------------------------------------------
// cs[j] = dot(kh[j,:], w) * (log2e/32).  One block per key row, fp16 key.
// ---------------------------------------------------------------------------
__global__ void __launch_bounds__(256) cvec_kernel(
    const __half* __restrict__ kh, const float* __restrict__ w,
    float* __restrict__ cs)
{
    const size_t j = blockIdx.x;
    const int tid = threadIdx.x;
    const __half* kr = kh + j * SDK;
    float s = 0.f;
    #pragma unroll
    for (int t = 0; t < 4; t++) {
        int o = tid + t * 256;
        s += __half2float(kr[o]) * w[o];
    }
    #pragma unroll
    for (int off = 16; off; off >>= 1)
        s += __shfl_xor_sync(0xffffffffu, s, off);
    __shared__ float red[8];
    if ((tid & 31) == 0) red[tid >> 5] = s;
    __syncthreads();
    if (tid == 0) {
        float t = 0.f;
        #pragma unroll
        for (int k = 0; k < 8; k++) t += red[k];
        cs[j] = t * (0.03125f * LOG2E);
    }
}

// ---------------------------------------------------------------------------
// rs[i] = 1 / sum(part[i][0..8))   (deterministic, fixed order)
// ---------------------------------------------------------------------------
__global__ void __launch_bounds__(256) rowinv_kernel(
    const float* __restrict__ part, float* __restrict__ rs)
{
    int i = blockIdx.x * 256 + threadIdx.x;
    const float* p = part + (size_t)i * 8;
    float s = ((p[0] + p[1]) + (p[2] + p[3])) + ((p[4] + p[5]) + (p[6] + p[7]));
    rs[i] = 1.f / s;
}

// ---------------------------------------------------------------------------
// kernel_launch
// ---------------------------------------------------------------------------
extern "C" void kernel_launch(void* const* d_in, const int* in_sizes, int n_in,
                              void* d_out, int out_size)
{
    const float* query = (const float*)d_in[0];
    const float* key   = (const float*)d_in[1];
    const float* Wq    = (const float*)d_in[2];
    const float* bq    = (const float*)d_in[3];
    const float* Wk    = (const float*)d_in[4];
    const float* bk    = (const float*)d_in[5];   // vanishes under softmax
    const float* Wv    = (const float*)d_in[6];
    const float* bv    = (const float*)d_in[7];
    float* out = (float*)d_out;
    (void)bk;

    __half *qh,*kh,*wq16,*wk16,*wvt,*M2,*Kred,*Vth,*Sf;
    float *w,*cs,*part,*rs;
    cudaGetSymbolAddress((void**)&qh,   g_qh);
    cudaGetSymbolAddress((void**)&kh,   g_kh);
    cudaGetSymbolAddress((void**)&wq16, g_wq16);
    cudaGetSymbolAddress((void**)&wk16, g_wk16);
    cudaGetSymbolAddress((void**)&wvt,  g_wvt);
    cudaGetSymbolAddress((void**)&M2,   g_M2);
    cudaGetSymbolAddress((void**)&Kred, g_Kred);
    cudaGetSymbolAddress((void**)&Vth,  g_Vth);
    cudaGetSymbolAddress((void**)&Sf,   g_Sf);
    cudaGetSymbolAddress((void**)&w,    g_w);
    cudaGetSymbolAddress((void**)&cs,   g_cs);
    cudaGetSymbolAddress((void**)&part, g_part);
    cudaGetSymbolAddress((void**)&rs,   g_rs);

    cudaFuncSetAttribute(mma_gemm<2,0>, cudaFuncAttributeMaxDynamicSharedMemorySize, GEMM_SMEM);
    cudaFuncSetAttribute(mma_gemm<2,2>, cudaFuncAttributeMaxDynamicSharedMemorySize, GEMM_SMEM);
    cudaFuncSetAttribute(mma_gemm<3,1>, cudaFuncAttributeMaxDynamicSharedMemorySize, GEMM_SMEM);
    cudaFuncSetAttribute(mma_gemm<0,3>, cudaFuncAttributeMaxDynamicSharedMemorySize, GEMM_SMEM);

    // 1. all fp32->fp16 converts in ONE launch (query, key, Wq, Wk)
    {
        const unsigned Bq  = (unsigned)((size_t)NB * SLQ * SDQ / 2048);  // 12288
        const unsigned Bk  = (unsigned)((size_t)NB * SLK * SDK / 2048);  // 16384
        const unsigned Bwq = (unsigned)((size_t)SDQ * SDK / 2048);       // 384
        const unsigned Bwk = (unsigned)((size_t)SDK * SDK / 2048);       // 512
        cvt4_kernel<<<Bq + Bk + Bwq + Bwk, 256>>>(
            query, qh, Bq, key, kh, Bk, Wq, wq16, Bwq, Wk, wk16);
    }
    transpose_cvt_kernel<<<dim3(SDK/32, SDK/32), dim3(32,8)>>>(Wv, wvt, SDK, SDK);

    // 2. bias column (log2-domain): w = Wk@bq ; cs = (kh@w) * log2e/32
    wvec_kernel<<<SDK, 256>>>(Wk, bq, w);
    cvec_kernel<<<NB*SLK, 256>>>(kh, w, cs);

    // 3. M2 = Wq @ Wk^T  (M=768, N=1024, K=1024) -> fp16
    mma_gemm<2,0><<<dim3(SDK/BN, SDQ/BM, 1), 256, GEMM_SMEM>>>(
        wq16, wk16, nullptr, nullptr, M2, SDK, SDK, 1.f, 0, 0, 0, 0);

    // 4. Kred = key @ M2^T  (M=32768, N=768, K=1024) -> fp16
    mma_gemm<2,0><<<dim3(SDQ/BN, (NB*SLK)/BM, 1), 256, GEMM_SMEM>>>(
        kh, M2, nullptr, nullptr, Kred, SDQ, SDK, 1.f, 0, 0, 0, 0);

    // 5. V projection, transposed out: Vt[b][d][t] (M=1024, N=2048, K=1024)
    mma_gemm<2,2><<<dim3(SLK/BN, SDK/BM, NB), 256, GEMM_SMEM>>>(
        wvt, kh, bv, nullptr, Vth,
        SLK, SDK, 1.f, 0, (long)SLK*SDK, (long)SDK*SLK, 0);

    // 6. Sf = exp2(query @ Kred^T * log2e/32 + cs), plus deterministic
    //    per-CTA row-sum partials
    mma_gemm<3,1><<<dim3(SLK/BN, SLQ/BM, NB), 256, GEMM_SMEM>>>(
        qh, Kred, cs, part, Sf,
        SLK, SDQ, 0.03125f * LOG2E,
        (long)SLQ*SDQ, (long)SLK*SDQ, (long)SLQ*SLK, SLK);

    // 7. row-sum reciprocals
    rowinv_kernel<<<NB*SLQ/256, 256>>>(part, rs);

    // 8. out = (Sf @ Vt^T) * rs[row]  (M=2048, N=1024, K=2048 per batch)
    mma_gemm<0,3><<<dim3(SDK/BN, SLQ/BM, NB), 256, GEMM_SMEM>>>(
        Sf, Vth, rs, out, nullptr,
        SDK, SLK, 1.f, (long)SLQ*SLK, (long)SDK*SLK, (long)SLQ*SDK, SLQ);
}